// round 9
// baseline (speedup 1.0000x reference)
#include <cuda_runtime.h>
#include <math.h>

// ============================================================================
// Problem constants
// ============================================================================
#define B_     2
#define S_     2048
#define IN_DIM 1024
#define P_DIM  512
#define H_     8
#define HD_    64
#define NPENTA 1024
#define KNEI   128
#define ROWS   (B_ * S_)        // 4096
#define EPS_   1e-5f

#define PAD    20               // smem row stride (floats): 16B-aligned rows,
                                // conflict-free ldmatrix (20r mod 32 distinct spans)

// ============================================================================
// Scratch (static device globals — no runtime allocation)
// ============================================================================
__device__ float g_Xh[ROWS * IN_DIM];             // pre-split X
__device__ float g_Xl[ROWS * IN_DIM];
__device__ float g_pWh[P_DIM * IN_DIM];           // projW^T pre-split [N][K]
__device__ float g_pWl[P_DIM * IN_DIM];
__device__ float g_qWh[3 * P_DIM * P_DIM];        // qkvW^T pre-split [N][K]
__device__ float g_qWl[3 * P_DIM * P_DIM];
__device__ float g_centh[NPENTA * P_DIM];         // centroids pre-split [N][K]
__device__ float g_centl[NPENTA * P_DIM];
__device__ float g_zh[ROWS * P_DIM];              // z pre-split
__device__ float g_zl[ROWS * P_DIM];
__device__ float g_zpre[ROWS * P_DIM];
__device__ float g_pval[ROWS * 16];
__device__ int   g_pidx[ROWS * 16];
__device__ int   g_anchor[ROWS];
__device__ int   g_routes[B_ * NPENTA * KNEI];
__device__ float g_qkv[ROWS * 3 * P_DIM];
__device__ float g_att[ROWS * P_DIM];
__device__ float g_attpart[B_ * 16 * P_DIM];
__device__ float g_attmean[B_ * P_DIM];
__device__ float g_pooled[B_ * P_DIM];
__device__ float g_h[B_ * 1024];

// ============================================================================
// Helpers
// ============================================================================
__device__ __forceinline__ float gelu_exact(float x) {
    return 0.5f * x * (1.0f + erff(x * 0.70710678118654752440f));
}

__device__ __forceinline__ float block_sum(float v, float* red, int n, int tid) {
    red[tid] = v;
    __syncthreads();
    for (int s = n >> 1; s > 0; s >>= 1) {
        if (tid < s) red[tid] += red[tid + s];
        __syncthreads();
    }
    float r = red[0];
    __syncthreads();
    return r;
}

__device__ __forceinline__ float warp_sum(float v) {
#pragma unroll
    for (int o = 16; o; o >>= 1) v += __shfl_xor_sync(0xffffffffu, v, o);
    return v;
}

__device__ __forceinline__ unsigned cvt_tf32(float x) {
    unsigned r;
    asm("cvt.rna.tf32.f32 %0, %1;" : "=r"(r) : "f"(x));
    return r;
}

__device__ __forceinline__ void split1(float x, float& h, float& l) {
    h = __uint_as_float(cvt_tf32(x));
    l = __uint_as_float(cvt_tf32(x - h));
}

__device__ __forceinline__ void mma_tf32(float* c, const unsigned* a, const unsigned* b) {
    asm volatile(
        "mma.sync.aligned.m16n8k8.row.col.f32.tf32.tf32.f32 "
        "{%0,%1,%2,%3}, {%4,%5,%6,%7}, {%8,%9}, {%0,%1,%2,%3};"
        : "+f"(c[0]), "+f"(c[1]), "+f"(c[2]), "+f"(c[3])
        : "r"(a[0]), "r"(a[1]), "r"(a[2]), "r"(a[3]), "r"(b[0]), "r"(b[1]));
}

__device__ __forceinline__ void ldsm4(unsigned* r, unsigned saddr) {
    asm volatile(
        "ldmatrix.sync.aligned.m8n8.x4.shared.b16 {%0,%1,%2,%3}, [%4];"
        : "=r"(r[0]), "=r"(r[1]), "=r"(r[2]), "=r"(r[3]) : "r"(saddr));
}

__device__ __forceinline__ void cpasync16(unsigned saddr, const float* g) {
    asm volatile("cp.async.cg.shared.global [%0], [%1], 16;" :: "r"(saddr), "l"(g));
}
__device__ __forceinline__ void cp_commit() {
    asm volatile("cp.async.commit_group;");
}
__device__ __forceinline__ void cp_wait0() {
    asm volatile("cp.async.wait_group 0;");
}

// ============================================================================
// Elementwise split:  src -> (hi, lo)
// ============================================================================
__global__ void k_split(const float* __restrict__ src, float* __restrict__ dh,
                        float* __restrict__ dl, int n4) {
    int i = blockIdx.x * 256 + threadIdx.x;
    if (i >= n4) return;
    float4 v = ((const float4*)src)[i];
    float4 h, l;
    split1(v.x, h.x, l.x); split1(v.y, h.y, l.y);
    split1(v.z, h.z, l.z); split1(v.w, h.w, l.w);
    ((float4*)dh)[i] = h;
    ((float4*)dl)[i] = l;
}

// ============================================================================
// Transpose + split:  W[K][N] -> T{hi,lo}[N][K]   (32x32 smem tiles)
// ============================================================================
__global__ void k_splitT(const float* __restrict__ W, float* __restrict__ th,
                         float* __restrict__ tl, int K, int N) {
    __shared__ float tile[32][33];
    int n0 = blockIdx.x * 32, k0 = blockIdx.y * 32;
    int tx = threadIdx.x, ty = threadIdx.y;   // 32 x 8
    for (int i = ty; i < 32; i += 8)
        tile[i][tx] = W[(size_t)(k0 + i) * N + n0 + tx];
    __syncthreads();
    for (int i = ty; i < 32; i += 8) {
        float v = tile[tx][i];                 // = W[k0+tx][n0+i]
        float h, l;
        split1(v, h, l);
        th[(size_t)(n0 + i) * K + k0 + tx] = h;
        tl[(size_t)(n0 + i) * K + k0 + tx] = l;
    }
}

// ============================================================================
// centroids = normalize(mean over 5 vertices) -> pre-split
// ============================================================================
__global__ void k_cent(const float* __restrict__ penta) {
    __shared__ float red[256];
    int p = blockIdx.x, tid = threadIdx.x;
    float v[2];
    float ss = 0.f;
#pragma unroll
    for (int r = 0; r < 2; r++) {
        int d = tid + r * 256;
        float s = 0.f;
#pragma unroll
        for (int i = 0; i < 5; i++) s += penta[(p * 5 + i) * P_DIM + d];
        v[r] = s / 5.0f;
        ss += v[r] * v[r];
    }
    float tot = block_sum(ss, red, 256, tid);
    float den = fmaxf(sqrtf(tot), 1e-12f);
#pragma unroll
    for (int r = 0; r < 2; r++) {
        float h, l;
        split1(v[r] / den, h, l);
        g_centh[p * P_DIM + tid + r * 256] = h;
        g_centl[p * P_DIM + tid + r * 256] = l;
    }
}

// ============================================================================
// 3xTF32 tensor-core GEMM. Operands PRE-SPLIT in global, ALL in [rows][K]
// layout (A: M rows, B: N rows). cp.async fills smem; ldmatrix feeds MMA.
// BM=128, BN=64, BK=16, 256 threads = 8 warps (4m x 2n), warp tile 32x32.
// Inner loop per k8: 8 LDSM.x4 + 24 HMMA per warp. No CVT, no staging.
// ============================================================================
template <int N, int K, bool BIAS, bool ARGMAX>
__device__ __forceinline__ void mma_gemm_body(const float* __restrict__ Ahg,
                                              const float* __restrict__ Alg,
                                              const float* __restrict__ Bhg,
                                              const float* __restrict__ Blg,
                                              const float* __restrict__ bias,
                                              float* __restrict__ C) {
    __shared__ float Ah[2][128][PAD];
    __shared__ float Al[2][128][PAD];
    __shared__ float Bh[2][64][PAD];
    __shared__ float Bl[2][64][PAD];

    const int tid  = threadIdx.x;
    const int lane = tid & 31;
    const int warp = tid >> 5;
    const int wm = warp >> 1, wn = warp & 1;
    const int row0 = blockIdx.y * 128, col0 = blockIdx.x * 64;

    // cp.async chunk mapping: chunk c -> row c>>2, kcol (c&3)*4
    const int cr = tid >> 2;            // 0..63
    const int ck = (tid & 3) * 4;

    float acc[2][4][4];
#pragma unroll
    for (int mt = 0; mt < 2; mt++)
#pragma unroll
        for (int nt = 0; nt < 4; nt++)
#pragma unroll
            for (int r = 0; r < 4; r++) acc[mt][nt][r] = 0.f;

    // ldmatrix lane address offsets (bytes); rows are 16B-aligned (PAD=20)
    const unsigned offA = ((unsigned)(wm * 32 + (lane & 15)) * PAD + (unsigned)((lane >> 4) * 4)) * 4u;
    const int brow = (lane & 7) + ((lane >> 4) << 3);
    const int bcol = ((lane >> 3) & 1) * 4;
    const unsigned offB = ((unsigned)(wn * 32 + brow) * PAD + (unsigned)bcol) * 4u;
    const unsigned baseAh = (unsigned)__cvta_generic_to_shared(&Ah[0][0][0]);
    const unsigned baseAl = (unsigned)__cvta_generic_to_shared(&Al[0][0][0]);
    const unsigned baseBh = (unsigned)__cvta_generic_to_shared(&Bh[0][0][0]);
    const unsigned baseBl = (unsigned)__cvta_generic_to_shared(&Bl[0][0][0]);
    const unsigned A_TILE = 128u * PAD * 4u;
    const unsigned B_TILE = 64u * PAD * 4u;
    const unsigned MT_OFF = 16u * PAD * 4u;

    // per-thread smem dst offsets (within a stage)
    const unsigned sA0 = ((unsigned)cr * PAD + (unsigned)ck) * 4u;
    const unsigned sA1 = ((unsigned)(cr + 64) * PAD + (unsigned)ck) * 4u;
    const unsigned sB0 = sA0;
    // per-thread global src offsets (k-relative)
    const float* gA0h = Ahg + (size_t)(row0 + cr) * K + ck;
    const float* gA1h = Ahg + (size_t)(row0 + cr + 64) * K + ck;
    const float* gA0l = Alg + (size_t)(row0 + cr) * K + ck;
    const float* gA1l = Alg + (size_t)(row0 + cr + 64) * K + ck;
    const float* gB0h = Bhg + (size_t)(col0 + cr) * K + ck;
    const float* gB0l = Blg + (size_t)(col0 + cr) * K + ck;

    // ---- issue stage 0
    {
        const unsigned aS = 0, bS = 0;
        cpasync16(baseAh + aS + sA0, gA0h);
        cpasync16(baseAh + aS + sA1, gA1h);
        cpasync16(baseAl + aS + sA0, gA0l);
        cpasync16(baseAl + aS + sA1, gA1l);
        cpasync16(baseBh + bS + sB0, gB0h);
        cpasync16(baseBl + bS + sB0, gB0l);
        cp_commit();
    }
    cp_wait0();
    __syncthreads();

    int buf = 0;
    for (int k0 = 16; k0 < K + 16; k0 += 16) {
        if (k0 < K) {
            const unsigned aS = (unsigned)(buf ^ 1) * A_TILE;
            const unsigned bS = (unsigned)(buf ^ 1) * B_TILE;
            cpasync16(baseAh + aS + sA0, gA0h + k0);
            cpasync16(baseAh + aS + sA1, gA1h + k0);
            cpasync16(baseAl + aS + sA0, gA0l + k0);
            cpasync16(baseAl + aS + sA1, gA1l + k0);
            cpasync16(baseBh + bS + sB0, gB0h + k0);
            cpasync16(baseBl + bS + sB0, gB0l + k0);
            cp_commit();
        }
        // ---- compute on buf
        const unsigned aSt = (unsigned)buf * A_TILE;
        const unsigned bSt = (unsigned)buf * B_TILE;
#pragma unroll
        for (int kc = 0; kc < 2; kc++) {
            unsigned ah[2][4], alr[2][4], bh[2][4], blr[2][4];
#pragma unroll
            for (int mt = 0; mt < 2; mt++) {
                unsigned ad = aSt + offA + (unsigned)mt * MT_OFF + (unsigned)(kc * 32);
                ldsm4(ah[mt],  baseAh + ad);
                ldsm4(alr[mt], baseAl + ad);
            }
#pragma unroll
            for (int np = 0; np < 2; np++) {
                unsigned bd = bSt + offB + (unsigned)np * MT_OFF + (unsigned)(kc * 32);
                ldsm4(bh[np],  baseBh + bd);
                ldsm4(blr[np], baseBl + bd);
            }
#pragma unroll
            for (int mt = 0; mt < 2; mt++)
#pragma unroll
                for (int np = 0; np < 2; np++)
#pragma unroll
                    for (int hf = 0; hf < 2; hf++) {
                        float* c = acc[mt][np * 2 + hf];
                        mma_tf32(c, ah[mt],  &bh[np][hf * 2]);
                        mma_tf32(c, alr[mt], &bh[np][hf * 2]);
                        mma_tf32(c, ah[mt],  &blr[np][hf * 2]);
                    }
        }
        if (k0 < K) cp_wait0();
        __syncthreads();
        buf ^= 1;
    }

    if constexpr (ARGMAX) {
        __shared__ float s_v[128][2];
        __shared__ int   s_c[128][2];
#pragma unroll
        for (int mt = 0; mt < 2; mt++) {
#pragma unroll
            for (int half = 0; half < 2; half++) {
                const int rloc = wm * 32 + mt * 16 + (lane >> 2) + half * 8;
                float best = -1e30f;
                int bc = 0;
#pragma unroll
                for (int nt = 0; nt < 4; nt++) {
                    const int cl = wn * 32 + nt * 8 + (lane & 3) * 2;
                    float v0 = acc[mt][nt][half * 2];
                    float v1 = acc[mt][nt][half * 2 + 1];
                    if (v0 > best) { best = v0; bc = cl; }
                    if (v1 > best) { best = v1; bc = cl + 1; }
                }
#pragma unroll
                for (int o = 1; o < 4; o <<= 1) {
                    float ov = __shfl_xor_sync(0xffffffffu, best, o);
                    int   oc = __shfl_xor_sync(0xffffffffu, bc, o);
                    if (ov > best || (ov == best && oc < bc)) { best = ov; bc = oc; }
                }
                if ((lane & 3) == 0) { s_v[rloc][wn] = best; s_c[rloc][wn] = bc; }
            }
        }
        __syncthreads();
        if (tid < 128) {
            float best = s_v[tid][0];
            int bc = s_c[tid][0];
            if (s_v[tid][1] > best) { best = s_v[tid][1]; bc = s_c[tid][1]; }
            g_pval[(size_t)(row0 + tid) * 16 + blockIdx.x] = best;
            g_pidx[(size_t)(row0 + tid) * 16 + blockIdx.x] = col0 + bc;
        }
    } else {
#pragma unroll
        for (int mt = 0; mt < 2; mt++) {
            const int r0 = row0 + wm * 32 + mt * 16 + (lane >> 2);
#pragma unroll
            for (int nt = 0; nt < 4; nt++) {
                const int cc = col0 + wn * 32 + nt * 8 + (lane & 3) * 2;
                float b0 = 0.f, b1 = 0.f;
                if (BIAS) { b0 = bias[cc]; b1 = bias[cc + 1]; }
                float2* p0 = (float2*)&C[(size_t)r0 * N + cc];
                float2* p1 = (float2*)&C[(size_t)(r0 + 8) * N + cc];
                *p0 = make_float2(acc[mt][nt][0] + b0, acc[mt][nt][1] + b1);
                *p1 = make_float2(acc[mt][nt][2] + b0, acc[mt][nt][3] + b1);
            }
        }
    }
}

__global__ void __launch_bounds__(256)
k_gemm_proj(const float* __restrict__ b) {
    mma_gemm_body<P_DIM, IN_DIM, true, false>(g_Xh, g_Xl, g_pWh, g_pWl, b, g_zpre);
}
__global__ void __launch_bounds__(256) k_gemm_scores() {
    mma_gemm_body<NPENTA, P_DIM, false, true>(g_zh, g_zl, g_centh, g_centl, nullptr, nullptr);
}
__global__ void __launch_bounds__(256)
k_gemm_qkv(const float* __restrict__ b) {
    mma_gemm_body<3 * P_DIM, P_DIM, true, false>(g_zh, g_zl, g_qWh, g_qWl, b, g_qkv);
}

// ============================================================================
// LayerNorm + GELU + L2-normalize per row (512) -> pre-split z
// ============================================================================
__global__ void __launch_bounds__(128)
k_lgn(const float* __restrict__ gam, const float* __restrict__ bet) {
    __shared__ float wred[4];
    int row = blockIdx.x, tid = threadIdx.x;
    int lane = tid & 31, warp = tid >> 5;
    const float4* src = (const float4*)(g_zpre + (size_t)row * P_DIM);
    float4 x = src[tid];
    float s = warp_sum(x.x + x.y + x.z + x.w);
    if (lane == 0) wred[warp] = s;
    __syncthreads();
    float mu = (wred[0] + wred[1] + wred[2] + wred[3]) * (1.0f / 512.0f);
    __syncthreads();
    float4 d = make_float4(x.x - mu, x.y - mu, x.z - mu, x.w - mu);
    s = warp_sum(d.x * d.x + d.y * d.y + d.z * d.z + d.w * d.w);
    if (lane == 0) wred[warp] = s;
    __syncthreads();
    float var = (wred[0] + wred[1] + wred[2] + wred[3]) * (1.0f / 512.0f);
    __syncthreads();
    float rs = rsqrtf(var + EPS_);
    float4 gv = ((const float4*)gam)[tid];
    float4 bv = ((const float4*)bet)[tid];
    float4 hh;
    hh.x = gelu_exact(d.x * rs * gv.x + bv.x);
    hh.y = gelu_exact(d.y * rs * gv.y + bv.y);
    hh.z = gelu_exact(d.z * rs * gv.z + bv.z);
    hh.w = gelu_exact(d.w * rs * gv.w + bv.w);
    s = warp_sum(hh.x * hh.x + hh.y * hh.y + hh.z * hh.z + hh.w * hh.w);
    if (lane == 0) wred[warp] = s;
    __syncthreads();
    float nrm = sqrtf(wred[0] + wred[1] + wred[2] + wred[3]);
    float inv = 1.0f / fmaxf(nrm, 1e-12f);
    float4 zh, zl;
    split1(hh.x * inv, zh.x, zl.x);
    split1(hh.y * inv, zh.y, zl.y);
    split1(hh.z * inv, zh.z, zl.z);
    split1(hh.w * inv, zh.w, zl.w);
    ((float4*)(g_zh + (size_t)row * P_DIM))[tid] = zh;
    ((float4*)(g_zl + (size_t)row * P_DIM))[tid] = zl;
}

// ============================================================================
// Combine 16 col-block argmax partials (ascending, strict > = first index)
// ============================================================================
__global__ void k_anchor_reduce() {
    int row = blockIdx.x * 256 + threadIdx.x;
    if (row >= ROWS) return;
    float best = g_pval[(size_t)row * 16];
    int bi = g_pidx[(size_t)row * 16];
#pragma unroll
    for (int c = 1; c < 16; c++) {
        float v = g_pval[(size_t)row * 16 + c];
        if (v > best) { best = v; bi = g_pidx[(size_t)row * 16 + c]; }
    }
    g_anchor[row] = bi;
}

// ============================================================================
// Exact 128-NN per (batch, anchor) via histogram select on key
// (dist_bits<<32)|idx — same set as jax top_k(-dist) incl. tie-breaks.
// ============================================================================
__global__ void __launch_bounds__(256) k_topk(const float* __restrict__ positions) {
    __shared__ unsigned int db[S_];
    __shared__ unsigned int hist[2048];
    __shared__ unsigned long long cand[S_];
    __shared__ int scan[256];
    __shared__ int sb[4];
    int blk = blockIdx.x;
    int b = blk >> 10;
    int a = blk & 1023;
    int tid = threadIdx.x;
    if (tid == 0) { sb[2] = 0; sb[3] = 0; }
    float pq = positions[a];
    for (int i = tid; i < 2048; i += 256) hist[i] = 0;
    __syncthreads();
    for (int i = tid; i < S_; i += 256) {
        float p = positions[g_anchor[b * S_ + i]];
        unsigned int u = __float_as_uint(fabsf(pq - p));
        db[i] = u;
        atomicAdd(&hist[u >> 21], 1u);
    }
    __syncthreads();
    int base = tid * 8;
    unsigned int c[8];
    int loc = 0;
#pragma unroll
    for (int j = 0; j < 8; j++) { c[j] = hist[base + j]; loc += (int)c[j]; }
    int v = loc;
    scan[tid] = v;
    __syncthreads();
    for (int off = 1; off < 256; off <<= 1) {
        int t = (tid >= off) ? scan[tid - off] : 0;
        __syncthreads();
        v += t;
        scan[tid] = v;
        __syncthreads();
    }
    int run = v - loc;
#pragma unroll
    for (int j = 0; j < 8; j++) {
        int cnt = (int)c[j];
        if (run < KNEI && run + cnt >= KNEI) { sb[0] = base + j; sb[1] = run; }
        run += cnt;
    }
    __syncthreads();
    unsigned int bstar = (unsigned int)sb[0];
    int c0 = sb[1];
    int out = blk * KNEI;
    for (int i = tid; i < S_; i += 256) {
        unsigned int bkt = db[i] >> 21;
        if (bkt < bstar) {
            int s2 = atomicAdd(&sb[2], 1);
            g_routes[out + s2] = i;
        } else if (bkt == bstar) {
            int cp = atomicAdd(&sb[3], 1);
            cand[cp] = ((unsigned long long)db[i] << 32) | (unsigned int)i;
        }
    }
    __syncthreads();
    int ncand = sb[3];
    int need = KNEI - c0;
    int P = 1;
    while (P < ncand) P <<= 1;
    if (P < 2) P = 2;
    for (int i = ncand + tid; i < P; i += 256) cand[i] = 0xFFFFFFFFFFFFFFFFull;
    __syncthreads();
    for (int len = 2; len <= P; len <<= 1) {
        for (int j = len >> 1; j > 0; j >>= 1) {
            for (int i = tid; i < P; i += 256) {
                int p = i ^ j;
                if (p > i) {
                    bool up = ((i & len) == 0);
                    unsigned long long x = cand[i], y = cand[p];
                    if ((x > y) == up) { cand[i] = y; cand[p] = x; }
                }
            }
            __syncthreads();
        }
    }
    for (int r = tid; r < need; r += 256) g_routes[out + c0 + r] = (int)(cand[r] & 0xffffffffu);
}

// ============================================================================
// Gathered attention: block per (b,q); warp per head, barrier-free mainloop.
// ============================================================================
__global__ void __launch_bounds__(256) k_attention() {
    __shared__ int   rbase[KNEI];
    __shared__ float sc[H_][KNEI];
    int row = blockIdx.x;
    int b = row >> 11;
    int tid = threadIdx.x;
    int warp = tid >> 5, lane = tid & 31;
    int anc = g_anchor[row];
    if (tid < KNEI)
        rbase[tid] = (b * S_ + g_routes[((b << 10) + anc) * KNEI + tid]) * (3 * P_DIM);
    __syncthreads();

    const int h = warp;
    const int hoff = h * HD_;
    const size_t qrow = (size_t)row * (3 * P_DIM);
    const int qd = (lane & 7) * 8;
    const int ng = lane >> 3;

    float4 q0 = *(const float4*)&g_qkv[qrow + hoff + qd];
    float4 q1 = *(const float4*)&g_qkv[qrow + hoff + qd + 4];

#pragma unroll 4
    for (int rep = 0; rep < 32; rep++) {
        int n = rep * 4 + ng;
        const float* kr = &g_qkv[(size_t)rbase[n] + P_DIM + hoff + qd];
        float4 k0 = *(const float4*)kr;
        float4 k1 = *(const float4*)(kr + 4);
        float s = q0.x * k0.x + q0.y * k0.y + q0.z * k0.z + q0.w * k0.w
                + q1.x * k1.x + q1.y * k1.y + q1.z * k1.z + q1.w * k1.w;
        s += __shfl_xor_sync(0xffffffffu, s, 4);
        s += __shfl_xor_sync(0xffffffffu, s, 2);
        s += __shfl_xor_sync(0xffffffffu, s, 1);
        if ((lane & 7) == 0) sc[h][n] = s * 0.125f;
    }
    __syncwarp();

    float v0 = sc[h][lane], v1 = sc[h][lane + 32];
    float v2 = sc[h][lane + 64], v3 = sc[h][lane + 96];
    float m = fmaxf(fmaxf(v0, v1), fmaxf(v2, v3));
#pragma unroll
    for (int o = 16; o; o >>= 1) m = fmaxf(m, __shfl_xor_sync(0xffffffffu, m, o));
    v0 = expf(v0 - m); v1 = expf(v1 - m); v2 = expf(v2 - m); v3 = expf(v3 - m);
    float ssum = warp_sum(v0 + v1 + v2 + v3);
    float inv = 1.0f / ssum;
    sc[h][lane] = v0; sc[h][lane + 32] = v1;
    sc[h][lane + 64] = v2; sc[h][lane + 96] = v3;
    __syncwarp();

    float2 acc = make_float2(0.f, 0.f);
    const int d2 = lane * 2;
#pragma unroll 4
    for (int i = 0; i < KNEI; i++) {
        float p = sc[h][i];
        float2 vv = *(const float2*)&g_qkv[(size_t)rbase[i] + 2 * P_DIM + hoff + d2];
        acc.x += p * vv.x;
        acc.y += p * vv.y;
    }
    float* dst = &g_att[(size_t)row * P_DIM + hoff + d2];
    dst[0] = acc.x * inv;
    dst[1] = acc.y * inv;
}

// ============================================================================
// Pooling + out projection folded after the mean
// ============================================================================
__global__ void k_attmean1() {
    int bb = blockIdx.x;
    int b  = bb >> 6;
    int dc = (bb >> 4) & 3;
    int sc = bb & 15;
    int d = dc * 128 + threadIdx.x;
    float s = 0.f;
    int base = (b * S_ + sc * 128) * P_DIM + d;
    for (int t = 0; t < 128; t++) s += g_att[base + t * P_DIM];
    g_attpart[(b * 16 + sc) * P_DIM + d] = s;
}
__global__ void k_attmean2() {
    int b = blockIdx.x >> 2, dc = blockIdx.x & 3;
    int d = dc * 128 + threadIdx.x;
    float s = 0.f;
#pragma unroll
    for (int p = 0; p < 16; p++) s += g_attpart[(b * 16 + p) * P_DIM + d];
    g_attmean[b * P_DIM + d] = s * (1.0f / (float)S_);
}
__global__ void k_pool(const float* __restrict__ outW, const float* __restrict__ outb) {
    __shared__ float am[P_DIM];
    int b = blockIdx.x, n = threadIdx.x;
    am[n] = g_attmean[b * P_DIM + n];
    __syncthreads();
    float acc = outb[n];
#pragma unroll 8
    for (int k = 0; k < P_DIM; k++) acc += am[k] * outW[k * P_DIM + n];
    g_pooled[b * P_DIM + n] = acc;
}

// ============================================================================
// Per-scale MLP heads
// ============================================================================
template <int TWOS>
__global__ void k_mlp1(const float* __restrict__ w1, const float* __restrict__ b1,
                       const float* __restrict__ gam, const float* __restrict__ bet) {
    __shared__ float pr[P_DIM];
    __shared__ float red[TWOS];
    int b = blockIdx.x, j = threadIdx.x;
    for (int k = j; k < P_DIM; k += TWOS) pr[k] = g_pooled[b * P_DIM + k];
    __syncthreads();
    float t = b1[j];
#pragma unroll 8
    for (int k = 0; k < P_DIM; k++) t += pr[k] * w1[k * TWOS + j];
    float mu = block_sum(t, red, TWOS, j) / (float)TWOS;
    float d = t - mu;
    float var = block_sum(d * d, red, TWOS, j) / (float)TWOS;
    float y = d * rsqrtf(var + EPS_) * gam[j] + bet[j];
    g_h[b * 1024 + j] = gelu_exact(y);
}

template <int TWOS, int SS, int OFF>
__global__ void k_mlp2(const float* __restrict__ w2, const float* __restrict__ b2,
                       float* __restrict__ out) {
    __shared__ float hr[TWOS];
    int b = blockIdx.x, j = threadIdx.x;
    for (int k = j; k < TWOS; k += SS) hr[k] = g_h[b * 1024 + k];
    __syncthreads();
    float acc = b2[j];
#pragma unroll 8
    for (int k = 0; k < TWOS; k++) acc += hr[k] * w2[k * SS + j];
    out[b * 896 + OFF + j] = acc;
}

// ============================================================================
// Launch
// ============================================================================
extern "C" void kernel_launch(void* const* d_in, const int* in_sizes, int n_in,
                              void* d_out, int out_size) {
    const float* X      = (const float*)d_in[0];
    const float* penta  = (const float*)d_in[1];
    const float* poss   = (const float*)d_in[2];
    const float* projW  = (const float*)d_in[3];
    const float* projb  = (const float*)d_in[4];
    const float* lng    = (const float*)d_in[5];
    const float* lnb    = (const float*)d_in[6];
    const float* qkvW   = (const float*)d_in[7];
    const float* qkvb   = (const float*)d_in[8];
    const float* outW   = (const float*)d_in[9];
    const float* outb   = (const float*)d_in[10];
    const float* w1a = (const float*)d_in[11]; const float* b1a = (const float*)d_in[12];
    const float* ga  = (const float*)d_in[13]; const float* bba = (const float*)d_in[14];
    const float* w2a = (const float*)d_in[15]; const float* b2a = (const float*)d_in[16];
    const float* w1b = (const float*)d_in[17]; const float* b1b = (const float*)d_in[18];
    const float* gb  = (const float*)d_in[19]; const float* bbb = (const float*)d_in[20];
    const float* w2b = (const float*)d_in[21]; const float* b2b = (const float*)d_in[22];
    const float* w1c = (const float*)d_in[23]; const float* b1c = (const float*)d_in[24];
    const float* gc  = (const float*)d_in[25]; const float* bbc = (const float*)d_in[26];
    const float* w2c = (const float*)d_in[27]; const float* b2c = (const float*)d_in[28];
    float* out = (float*)d_out;

    float* Xh; float* Xl; float* pWh; float* pWl; float* qWh; float* qWl;
    cudaGetSymbolAddress((void**)&Xh,  g_Xh);
    cudaGetSymbolAddress((void**)&Xl,  g_Xl);
    cudaGetSymbolAddress((void**)&pWh, g_pWh);
    cudaGetSymbolAddress((void**)&pWl, g_pWl);
    cudaGetSymbolAddress((void**)&qWh, g_qWh);
    cudaGetSymbolAddress((void**)&qWl, g_qWl);

    // operand pre-splits
    k_split<<<(ROWS * IN_DIM / 4 + 255) / 256, 256>>>(X, Xh, Xl, ROWS * IN_DIM / 4);
    k_splitT<<<dim3(P_DIM / 32, IN_DIM / 32), dim3(32, 8)>>>(projW, pWh, pWl, IN_DIM, P_DIM);
    k_splitT<<<dim3(3 * P_DIM / 32, P_DIM / 32), dim3(32, 8)>>>(qkvW, qWh, qWl, P_DIM, 3 * P_DIM);
    k_cent<<<NPENTA, 256>>>(penta);

    k_gemm_proj<<<dim3(P_DIM / 64, ROWS / 128), 256>>>(projb);
    k_lgn<<<ROWS, 128>>>(lng, lnb);
    k_gemm_scores<<<dim3(NPENTA / 64, ROWS / 128), 256>>>();
    k_anchor_reduce<<<ROWS / 256, 256>>>();
    k_gemm_qkv<<<dim3(3 * P_DIM / 64, ROWS / 128), 256>>>(qkvb);
    k_topk<<<B_ * NPENTA, 256>>>(poss);
    k_attention<<<ROWS, 256>>>();
    k_attmean1<<<128, 128>>>();
    k_attmean2<<<8, 128>>>();
    k_pool<<<B_, 512>>>(outW, outb);

    k_mlp1<256><<<B_, 256>>>(w1a, b1a, ga, bba);
    k_mlp2<256, 128, 0><<<B_, 128>>>(w2a, b2a, out);
    k_mlp1<512><<<B_, 512>>>(w1b, b1b, gb, bbb);
    k_mlp2<512, 256, 128><<<B_, 256>>>(w2b, b2b, out);
    k_mlp1<1024><<<B_, 1024>>>(w1c, b1c, gc, bbc);
    k_mlp2<1024, 512, 384><<<B_, 512>>>(w2c, b2c, out);
}

// round 10
// speedup vs baseline: 1.1460x; 1.1460x over previous
#include <cuda_runtime.h>
#include <math.h>

// ============================================================================
// Problem constants
// ============================================================================
#define B_     2
#define S_     2048
#define IN_DIM 1024
#define P_DIM  512
#define H_     8
#define HD_    64
#define NPENTA 1024
#define KNEI   128
#define ROWS   (B_ * S_)        // 4096
#define EPS_   1e-5f
#define TB_    8                // tokens per attention batch

#define PAD    20               // smem row stride (floats): 16B-aligned rows,
                                // conflict-free ldmatrix (20r mod 32 distinct spans)

// ============================================================================
// Scratch (static device globals — no runtime allocation)
// ============================================================================
__device__ float g_cent[NPENTA * P_DIM];
__device__ float g_zpre[ROWS * P_DIM];
__device__ float g_z[ROWS * P_DIM];
__device__ float g_pval[ROWS * 16];
__device__ int   g_pidx[ROWS * 16];
__device__ int   g_anchor[ROWS];
__device__ int   g_routes[B_ * NPENTA * KNEI];
__device__ int   g_gstart[B_ * NPENTA];
__device__ int   g_gcount[B_ * NPENTA];
__device__ int   g_order[B_ * S_];
__device__ float g_qkv[ROWS * 3 * P_DIM];
__device__ float g_att[ROWS * P_DIM];
__device__ float g_attpart[B_ * 16 * P_DIM];
__device__ float g_attmean[B_ * P_DIM];
__device__ float g_pooled[B_ * P_DIM];
__device__ float g_h[B_ * 1024];

// ============================================================================
// Helpers
// ============================================================================
__device__ __forceinline__ float gelu_exact(float x) {
    return 0.5f * x * (1.0f + erff(x * 0.70710678118654752440f));
}

__device__ __forceinline__ float block_sum(float v, float* red, int n, int tid) {
    red[tid] = v;
    __syncthreads();
    for (int s = n >> 1; s > 0; s >>= 1) {
        if (tid < s) red[tid] += red[tid + s];
        __syncthreads();
    }
    float r = red[0];
    __syncthreads();
    return r;
}

__device__ __forceinline__ float warp_sum(float v) {
#pragma unroll
    for (int o = 16; o; o >>= 1) v += __shfl_xor_sync(0xffffffffu, v, o);
    return v;
}

__device__ __forceinline__ unsigned cvt_tf32(float x) {
    unsigned r;
    asm("cvt.rna.tf32.f32 %0, %1;" : "=r"(r) : "f"(x));
    return r;
}

__device__ __forceinline__ void split1(float x, float& h, float& l) {
    h = __uint_as_float(cvt_tf32(x));
    l = __uint_as_float(cvt_tf32(x - h));
}

__device__ __forceinline__ void mma_tf32(float* c, const unsigned* a, const unsigned* b) {
    asm volatile(
        "mma.sync.aligned.m16n8k8.row.col.f32.tf32.tf32.f32 "
        "{%0,%1,%2,%3}, {%4,%5,%6,%7}, {%8,%9}, {%0,%1,%2,%3};"
        : "+f"(c[0]), "+f"(c[1]), "+f"(c[2]), "+f"(c[3])
        : "r"(a[0]), "r"(a[1]), "r"(a[2]), "r"(a[3]), "r"(b[0]), "r"(b[1]));
}

__device__ __forceinline__ void ldsm4(unsigned* r, unsigned saddr) {
    asm volatile(
        "ldmatrix.sync.aligned.m8n8.x4.shared.b16 {%0,%1,%2,%3}, [%4];"
        : "=r"(r[0]), "=r"(r[1]), "=r"(r[2]), "=r"(r[3]) : "r"(saddr));
}

// ============================================================================
// centroids = normalize(mean over 5 vertices)
// ============================================================================
__global__ void k_cent(const float* __restrict__ penta) {
    __shared__ float red[256];
    int p = blockIdx.x, tid = threadIdx.x;
    float v[2];
    float ss = 0.f;
#pragma unroll
    for (int r = 0; r < 2; r++) {
        int d = tid + r * 256;
        float s = 0.f;
#pragma unroll
        for (int i = 0; i < 5; i++) s += penta[(p * 5 + i) * P_DIM + d];
        v[r] = s / 5.0f;
        ss += v[r] * v[r];
    }
    float tot = block_sum(ss, red, 256, tid);
    float den = fmaxf(sqrtf(tot), 1e-12f);
#pragma unroll
    for (int r = 0; r < 2; r++) g_cent[p * P_DIM + tid + r * 256] = v[r] / den;
}

// ============================================================================
// 3xTF32 tensor-core GEMM, hi/lo pre-split into smem, ldmatrix fragments.
// (identical to the 839us R8 version)
// ============================================================================
template <int N, int K, bool TB, bool BIAS, bool ARGMAX>
__device__ __forceinline__ void mma_gemm_body(const float* __restrict__ A,
                                              const float* __restrict__ Bm,
                                              const float* __restrict__ bias,
                                              float* __restrict__ C) {
    __shared__ float Ah[2][128][PAD];
    __shared__ float Al[2][128][PAD];
    __shared__ float Bh[2][64][PAD];
    __shared__ float Bl[2][64][PAD];

    const int tid  = threadIdx.x;
    const int lane = tid & 31;
    const int warp = tid >> 5;
    const int wm = warp >> 1, wn = warp & 1;
    const int row0 = blockIdx.y * 128, col0 = blockIdx.x * 64;

    const int ar = tid >> 2;
    const int ac = (tid & 3) * 4;
    const int bk = tid >> 4;
    const int bn = (tid & 15) * 4;
    const int tn = tid >> 2;
    const int tk = (tid & 3) * 4;

    float acc[2][4][4];
#pragma unroll
    for (int mt = 0; mt < 2; mt++)
#pragma unroll
        for (int nt = 0; nt < 4; nt++)
#pragma unroll
            for (int r = 0; r < 4; r++) acc[mt][nt][r] = 0.f;

    const unsigned offA = ((unsigned)(wm * 32 + (lane & 15)) * PAD + (unsigned)((lane >> 4) * 4)) * 4u;
    const int brow = (lane & 7) + ((lane >> 4) << 3);
    const int bcol = ((lane >> 3) & 1) * 4;
    const unsigned offB = ((unsigned)(wn * 32 + brow) * PAD + (unsigned)bcol) * 4u;
    const unsigned baseAh = (unsigned)__cvta_generic_to_shared(&Ah[0][0][0]);
    const unsigned baseAl = (unsigned)__cvta_generic_to_shared(&Al[0][0][0]);
    const unsigned baseBh = (unsigned)__cvta_generic_to_shared(&Bh[0][0][0]);
    const unsigned baseBl = (unsigned)__cvta_generic_to_shared(&Bl[0][0][0]);
    const unsigned A_TILE = 128u * PAD * 4u;
    const unsigned B_TILE = 64u * PAD * 4u;
    const unsigned MT_OFF = 16u * PAD * 4u;

    float4 av0, av1, bvv;

    const int am_r = tid >> 1, am_c = (tid & 1) * 8;   // A: 128 x 16 (8 floats)
    av0 = *(const float4*)(A + (size_t)(row0 + am_r) * K + am_c);
    av1 = *(const float4*)(A + (size_t)(row0 + am_r) * K + am_c + 4);
    if (!TB) bvv = *(const float4*)(Bm + (size_t)bk * N + col0 + bn);
    else     bvv = *(const float4*)(Bm + (size_t)(col0 + tn) * K + tk);

    {
        float a0[4] = {av0.x, av0.y, av0.z, av0.w};
        float a1[4] = {av1.x, av1.y, av1.z, av1.w};
#pragma unroll
        for (int j = 0; j < 4; j++) {
            float h, l;
            split1(a0[j], h, l);
            Ah[0][am_r][am_c + j] = h; Al[0][am_r][am_c + j] = l;
            split1(a1[j], h, l);
            Ah[0][am_r][am_c + 4 + j] = h; Al[0][am_r][am_c + 4 + j] = l;
        }
        if (!TB) {
            float hb, lb;
            split1(bvv.x, hb, lb); Bh[0][bn + 0][bk] = hb; Bl[0][bn + 0][bk] = lb;
            split1(bvv.y, hb, lb); Bh[0][bn + 1][bk] = hb; Bl[0][bn + 1][bk] = lb;
            split1(bvv.z, hb, lb); Bh[0][bn + 2][bk] = hb; Bl[0][bn + 2][bk] = lb;
            split1(bvv.w, hb, lb); Bh[0][bn + 3][bk] = hb; Bl[0][bn + 3][bk] = lb;
        } else {
            float bb[4] = {bvv.x, bvv.y, bvv.z, bvv.w};
#pragma unroll
            for (int j = 0; j < 4; j++) {
                float h, l;
                split1(bb[j], h, l);
                Bh[0][tn][tk + j] = h; Bl[0][tn][tk + j] = l;
            }
        }
    }
    __syncthreads();

    int buf = 0;
    for (int k0 = 16; k0 < K + 16; k0 += 16) {
        if (k0 < K) {
            av0 = *(const float4*)(A + (size_t)(row0 + am_r) * K + k0 + am_c);
            av1 = *(const float4*)(A + (size_t)(row0 + am_r) * K + k0 + am_c + 4);
            if (!TB) bvv = *(const float4*)(Bm + (size_t)(k0 + bk) * N + col0 + bn);
            else     bvv = *(const float4*)(Bm + (size_t)(col0 + tn) * K + k0 + tk);
        }
        const unsigned aSt = (unsigned)buf * A_TILE;
        const unsigned bSt = (unsigned)buf * B_TILE;
#pragma unroll
        for (int kc = 0; kc < 2; kc++) {
            unsigned ah[2][4], alr[2][4], bh[2][4], blr[2][4];
#pragma unroll
            for (int mt = 0; mt < 2; mt++) {
                unsigned ad = aSt + offA + (unsigned)mt * MT_OFF + (unsigned)(kc * 32);
                ldsm4(ah[mt],  baseAh + ad);
                ldsm4(alr[mt], baseAl + ad);
            }
#pragma unroll
            for (int np = 0; np < 2; np++) {
                unsigned bd = bSt + offB + (unsigned)np * MT_OFF + (unsigned)(kc * 32);
                ldsm4(bh[np],  baseBh + bd);
                ldsm4(blr[np], baseBl + bd);
            }
#pragma unroll
            for (int mt = 0; mt < 2; mt++)
#pragma unroll
                for (int np = 0; np < 2; np++)
#pragma unroll
                    for (int hf = 0; hf < 2; hf++) {
                        float* c = acc[mt][np * 2 + hf];
                        mma_tf32(c, ah[mt],  &bh[np][hf * 2]);
                        mma_tf32(c, alr[mt], &bh[np][hf * 2]);
                        mma_tf32(c, ah[mt],  &blr[np][hf * 2]);
                    }
        }
        if (k0 < K) {
            const int nb = buf ^ 1;
            float a0[4] = {av0.x, av0.y, av0.z, av0.w};
            float a1[4] = {av1.x, av1.y, av1.z, av1.w};
#pragma unroll
            for (int j = 0; j < 4; j++) {
                float h, l;
                split1(a0[j], h, l);
                Ah[nb][am_r][am_c + j] = h; Al[nb][am_r][am_c + j] = l;
                split1(a1[j], h, l);
                Ah[nb][am_r][am_c + 4 + j] = h; Al[nb][am_r][am_c + 4 + j] = l;
            }
            if (!TB) {
                float hb, lb;
                split1(bvv.x, hb, lb); Bh[nb][bn + 0][bk] = hb; Bl[nb][bn + 0][bk] = lb;
                split1(bvv.y, hb, lb); Bh[nb][bn + 1][bk] = hb; Bl[nb][bn + 1][bk] = lb;
                split1(bvv.z, hb, lb); Bh[nb][bn + 2][bk] = hb; Bl[nb][bn + 2][bk] = lb;
                split1(bvv.w, hb, lb); Bh[nb][bn + 3][bk] = hb; Bl[nb][bn + 3][bk] = lb;
            } else {
                float bb[4] = {bvv.x, bvv.y, bvv.z, bvv.w};
#pragma unroll
                for (int j = 0; j < 4; j++) {
                    float h, l;
                    split1(bb[j], h, l);
                    Bh[nb][tn][tk + j] = h; Bl[nb][tn][tk + j] = l;
                }
            }
        }
        __syncthreads();
        buf ^= 1;
    }

    if constexpr (ARGMAX) {
        __shared__ float s_v[128][2];
        __shared__ int   s_c[128][2];
#pragma unroll
        for (int mt = 0; mt < 2; mt++) {
#pragma unroll
            for (int half = 0; half < 2; half++) {
                const int rloc = wm * 32 + mt * 16 + (lane >> 2) + half * 8;
                float best = -1e30f;
                int bc = 0;
#pragma unroll
                for (int nt = 0; nt < 4; nt++) {
                    const int cl = wn * 32 + nt * 8 + (lane & 3) * 2;
                    float v0 = acc[mt][nt][half * 2];
                    float v1 = acc[mt][nt][half * 2 + 1];
                    if (v0 > best) { best = v0; bc = cl; }
                    if (v1 > best) { best = v1; bc = cl + 1; }
                }
#pragma unroll
                for (int o = 1; o < 4; o <<= 1) {
                    float ov = __shfl_xor_sync(0xffffffffu, best, o);
                    int   oc = __shfl_xor_sync(0xffffffffu, bc, o);
                    if (ov > best || (ov == best && oc < bc)) { best = ov; bc = oc; }
                }
                if ((lane & 3) == 0) { s_v[rloc][wn] = best; s_c[rloc][wn] = bc; }
            }
        }
        __syncthreads();
        if (tid < 128) {
            float best = s_v[tid][0];
            int bc = s_c[tid][0];
            if (s_v[tid][1] > best) { best = s_v[tid][1]; bc = s_c[tid][1]; }
            g_pval[(size_t)(row0 + tid) * 16 + blockIdx.x] = best;
            g_pidx[(size_t)(row0 + tid) * 16 + blockIdx.x] = col0 + bc;
        }
    } else {
#pragma unroll
        for (int mt = 0; mt < 2; mt++) {
            const int r0 = row0 + wm * 32 + mt * 16 + (lane >> 2);
#pragma unroll
            for (int nt = 0; nt < 4; nt++) {
                const int cc = col0 + wn * 32 + nt * 8 + (lane & 3) * 2;
                float b0 = 0.f, b1 = 0.f;
                if (BIAS) { b0 = bias[cc]; b1 = bias[cc + 1]; }
                float2* p0 = (float2*)&C[(size_t)r0 * N + cc];
                float2* p1 = (float2*)&C[(size_t)(r0 + 8) * N + cc];
                *p0 = make_float2(acc[mt][nt][0] + b0, acc[mt][nt][1] + b1);
                *p1 = make_float2(acc[mt][nt][2] + b0, acc[mt][nt][3] + b1);
            }
        }
    }
}

__global__ void __launch_bounds__(256)
k_gemm_proj(const float* __restrict__ X, const float* __restrict__ W,
            const float* __restrict__ b) {
    mma_gemm_body<P_DIM, IN_DIM, false, true, false>(X, W, b, g_zpre);
}
__global__ void __launch_bounds__(256) k_gemm_scores() {
    mma_gemm_body<NPENTA, P_DIM, true, false, true>(g_z, g_cent, nullptr, nullptr);
}
__global__ void __launch_bounds__(256)
k_gemm_qkv(const float* __restrict__ W, const float* __restrict__ b) {
    mma_gemm_body<3 * P_DIM, P_DIM, false, true, false>(g_z, W, b, g_qkv);
}

// ============================================================================
// LayerNorm + GELU + L2-normalize per row (512). 128 threads, float4/thread.
// ============================================================================
__global__ void __launch_bounds__(128)
k_lgn(const float* __restrict__ gam, const float* __restrict__ bet) {
    __shared__ float wred[4];
    int row = blockIdx.x, tid = threadIdx.x;
    int lane = tid & 31, warp = tid >> 5;
    const float4* src = (const float4*)(g_zpre + (size_t)row * P_DIM);
    float4 x = src[tid];
    float s = warp_sum(x.x + x.y + x.z + x.w);
    if (lane == 0) wred[warp] = s;
    __syncthreads();
    float mu = (wred[0] + wred[1] + wred[2] + wred[3]) * (1.0f / 512.0f);
    __syncthreads();
    float4 d = make_float4(x.x - mu, x.y - mu, x.z - mu, x.w - mu);
    s = warp_sum(d.x * d.x + d.y * d.y + d.z * d.z + d.w * d.w);
    if (lane == 0) wred[warp] = s;
    __syncthreads();
    float var = (wred[0] + wred[1] + wred[2] + wred[3]) * (1.0f / 512.0f);
    __syncthreads();
    float rs = rsqrtf(var + EPS_);
    float4 gv = ((const float4*)gam)[tid];
    float4 bv = ((const float4*)bet)[tid];
    float4 hh;
    hh.x = gelu_exact(d.x * rs * gv.x + bv.x);
    hh.y = gelu_exact(d.y * rs * gv.y + bv.y);
    hh.z = gelu_exact(d.z * rs * gv.z + bv.z);
    hh.w = gelu_exact(d.w * rs * gv.w + bv.w);
    s = warp_sum(hh.x * hh.x + hh.y * hh.y + hh.z * hh.z + hh.w * hh.w);
    if (lane == 0) wred[warp] = s;
    __syncthreads();
    float nrm = sqrtf(wred[0] + wred[1] + wred[2] + wred[3]);
    float inv = 1.0f / fmaxf(nrm, 1e-12f);
    float4* dst = (float4*)(g_z + (size_t)row * P_DIM);
    dst[tid] = make_float4(hh.x * inv, hh.y * inv, hh.z * inv, hh.w * inv);
}

// ============================================================================
// Combine 16 col-block argmax partials (ascending, strict > = first index)
// ============================================================================
__global__ void k_anchor_reduce() {
    int row = blockIdx.x * 256 + threadIdx.x;
    if (row >= ROWS) return;
    float best = g_pval[(size_t)row * 16];
    int bi = g_pidx[(size_t)row * 16];
#pragma unroll
    for (int c = 1; c < 16; c++) {
        float v = g_pval[(size_t)row * 16 + c];
        if (v > best) { best = v; bi = g_pidx[(size_t)row * 16 + c]; }
    }
    g_anchor[row] = bi;
}

// ============================================================================
// Group tokens by anchor: per batch, histogram over 1024 anchors, exclusive
// scan, scatter token ids. Token order within a group is irrelevant (softmax
// per token is independent).
// ============================================================================
__global__ void __launch_bounds__(1024) k_group() {
    __shared__ int hist[NPENTA];
    __shared__ int scanb[NPENTA];
    __shared__ int offs[NPENTA];
    int b = blockIdx.x, tid = threadIdx.x;   // 1024 threads
    hist[tid] = 0;
    __syncthreads();
    int a0 = g_anchor[b * S_ + tid];
    int a1 = g_anchor[b * S_ + 1024 + tid];
    atomicAdd(&hist[a0], 1);
    atomicAdd(&hist[a1], 1);
    __syncthreads();
    int v = hist[tid];
    int inc = v;
    scanb[tid] = inc;
    __syncthreads();
    for (int off = 1; off < 1024; off <<= 1) {
        int t = (tid >= off) ? scanb[tid - off] : 0;
        __syncthreads();
        inc += t;
        scanb[tid] = inc;
        __syncthreads();
    }
    int start = inc - v;
    g_gstart[b * NPENTA + tid] = start;
    g_gcount[b * NPENTA + tid] = v;
    offs[tid] = start;
    __syncthreads();
    int p0 = atomicAdd(&offs[a0], 1);
    g_order[b * S_ + p0] = tid;
    int p1 = atomicAdd(&offs[a1], 1);
    g_order[b * S_ + p1] = 1024 + tid;
}

// ============================================================================
// Exact 128-NN per (batch, anchor) via histogram select. Skips unused anchors.
// ============================================================================
__global__ void __launch_bounds__(256) k_topk(const float* __restrict__ positions) {
    __shared__ unsigned int db[S_];
    __shared__ unsigned int hist[2048];
    __shared__ unsigned long long cand[S_];
    __shared__ int scan[256];
    __shared__ int sb[4];
    int blk = blockIdx.x;
    if (g_gcount[blk] == 0) return;   // no token uses this anchor
    int b = blk >> 10;
    int a = blk & 1023;
    int tid = threadIdx.x;
    if (tid == 0) { sb[2] = 0; sb[3] = 0; }
    float pq = positions[a];
    for (int i = tid; i < 2048; i += 256) hist[i] = 0;
    __syncthreads();
    for (int i = tid; i < S_; i += 256) {
        float p = positions[g_anchor[b * S_ + i]];
        unsigned int u = __float_as_uint(fabsf(pq - p));
        db[i] = u;
        atomicAdd(&hist[u >> 21], 1u);
    }
    __syncthreads();
    int base = tid * 8;
    unsigned int c[8];
    int loc = 0;
#pragma unroll
    for (int j = 0; j < 8; j++) { c[j] = hist[base + j]; loc += (int)c[j]; }
    int v = loc;
    scan[tid] = v;
    __syncthreads();
    for (int off = 1; off < 256; off <<= 1) {
        int t = (tid >= off) ? scan[tid - off] : 0;
        __syncthreads();
        v += t;
        scan[tid] = v;
        __syncthreads();
    }
    int run = v - loc;
#pragma unroll
    for (int j = 0; j < 8; j++) {
        int cnt = (int)c[j];
        if (run < KNEI && run + cnt >= KNEI) { sb[0] = base + j; sb[1] = run; }
        run += cnt;
    }
    __syncthreads();
    unsigned int bstar = (unsigned int)sb[0];
    int c0 = sb[1];
    int out = blk * KNEI;
    for (int i = tid; i < S_; i += 256) {
        unsigned int bkt = db[i] >> 21;
        if (bkt < bstar) {
            int s2 = atomicAdd(&sb[2], 1);
            g_routes[out + s2] = i;
        } else if (bkt == bstar) {
            int cp = atomicAdd(&sb[3], 1);
            cand[cp] = ((unsigned long long)db[i] << 32) | (unsigned int)i;
        }
    }
    __syncthreads();
    int ncand = sb[3];
    int need = KNEI - c0;
    int P = 1;
    while (P < ncand) P <<= 1;
    if (P < 2) P = 2;
    for (int i = ncand + tid; i < P; i += 256) cand[i] = 0xFFFFFFFFFFFFFFFFull;
    __syncthreads();
    for (int len = 2; len <= P; len <<= 1) {
        for (int j = len >> 1; j > 0; j >>= 1) {
            for (int i = tid; i < P; i += 256) {
                int p = i ^ j;
                if (p > i) {
                    bool up = ((i & len) == 0);
                    unsigned long long x = cand[i], y = cand[p];
                    if ((x > y) == up) { cand[i] = y; cand[p] = x; }
                }
            }
            __syncthreads();
        }
    }
    for (int r = tid; r < need; r += 256) g_routes[out + c0 + r] = (int)(cand[r] & 0xffffffffu);
}

// ============================================================================
// Grouped attention: block per (group=(b,anchor), head). K/V tiles staged in
// smem ONCE per group and served to all tokens of the group (identical
// neighbor sets). 64-neighbor chunks; up to TB_=8 tokens per inner batch.
// ============================================================================
__global__ void __launch_bounds__(256) k_attng() {
    __shared__ int   rbase[KNEI];
    __shared__ float tile[64][65];
    __shared__ float qb[TB_][64];
    __shared__ float scb[TB_][KNEI];
    __shared__ float sinv[TB_];
    __shared__ int   srow[TB_];
    int blk = blockIdx.x;
    int cnt = g_gcount[blk];
    if (cnt == 0) return;
    int b = blk >> 10;
    int h = blockIdx.y;
    int hoff = h * HD_;
    int start = g_gstart[blk];
    int tid = threadIdx.x, lane = tid & 31, warp = tid >> 5;

    if (tid < KNEI)
        rbase[tid] = (b * S_ + g_routes[blk * KNEI + tid]) * (3 * P_DIM);

    for (int tb = 0; tb < cnt; tb += TB_) {
        int nt = min(TB_, cnt - tb);
        if (tid < nt) srow[tid] = b * S_ + g_order[b * S_ + start + tb + tid];
        __syncthreads();   // rbase + srow visible
        // q batch
        for (int idx = tid; idx < nt * 64; idx += 256) {
            int t = idx >> 6, d = idx & 63;
            qb[t][d] = g_qkv[(size_t)srow[t] * (3 * P_DIM) + hoff + d];
        }
        // K chunks -> scores
#pragma unroll
        for (int c = 0; c < 2; c++) {
            __syncthreads();   // qb visible / tile free
            for (int e = tid; e < 64 * 64; e += 256) {
                int i = e >> 6, d = e & 63;
                tile[i][d] = g_qkv[(size_t)rbase[c * 64 + i] + P_DIM + hoff + d];
            }
            __syncthreads();
            for (int idx = tid; idx < nt * 64; idx += 256) {
                int t = idx >> 6, n = idx & 63;
                float s = 0.f;
#pragma unroll 8
                for (int d = 0; d < 64; d++) s += qb[t][d] * tile[n][d];
                scb[t][c * 64 + n] = s * 0.125f;
            }
        }
        __syncthreads();
        // softmax: warp w -> token w
        if (warp < nt) {
            float v0 = scb[warp][lane], v1 = scb[warp][lane + 32];
            float v2 = scb[warp][lane + 64], v3 = scb[warp][lane + 96];
            float m = fmaxf(fmaxf(v0, v1), fmaxf(v2, v3));
#pragma unroll
            for (int o = 16; o; o >>= 1) m = fmaxf(m, __shfl_xor_sync(0xffffffffu, m, o));
            v0 = expf(v0 - m); v1 = expf(v1 - m);
            v2 = expf(v2 - m); v3 = expf(v3 - m);
            float ssum = warp_sum(v0 + v1 + v2 + v3);
            scb[warp][lane] = v0; scb[warp][lane + 32] = v1;
            scb[warp][lane + 64] = v2; scb[warp][lane + 96] = v3;
            if (lane == 0) sinv[warp] = 1.0f / ssum;
        }
        // V chunks -> outputs
        float acc0 = 0.f, acc1 = 0.f;
        const int td = tid & 63;
        const int t0 = tid >> 6, t1 = 4 + (tid >> 6);
#pragma unroll
        for (int c = 0; c < 2; c++) {
            __syncthreads();   // scb/sinv visible / tile free
            for (int e = tid; e < 64 * 64; e += 256) {
                int i = e >> 6, d = e & 63;
                tile[i][d] = g_qkv[(size_t)rbase[c * 64 + i] + 2 * P_DIM + hoff + d];
            }
            __syncthreads();
            if (t0 < nt) {
                float s = acc0;
#pragma unroll 8
                for (int n = 0; n < 64; n++) s += scb[t0][c * 64 + n] * tile[n][td];
                acc0 = s;
            }
            if (t1 < nt) {
                float s = acc1;
#pragma unroll 8
                for (int n = 0; n < 64; n++) s += scb[t1][c * 64 + n] * tile[n][td];
                acc1 = s;
            }
        }
        if (t0 < nt) g_att[(size_t)srow[t0] * P_DIM + hoff + td] = acc0 * sinv[t0];
        if (t1 < nt) g_att[(size_t)srow[t1] * P_DIM + hoff + td] = acc1 * sinv[t1];
        __syncthreads();   // protect srow/scb/sinv before next token batch
    }
}

// ============================================================================
// Pooling + out projection folded after the mean
// ============================================================================
__global__ void k_attmean1() {
    int bb = blockIdx.x;
    int b  = bb >> 6;
    int dc = (bb >> 4) & 3;
    int sc = bb & 15;
    int d = dc * 128 + threadIdx.x;
    float s = 0.f;
    int base = (b * S_ + sc * 128) * P_DIM + d;
    for (int t = 0; t < 128; t++) s += g_att[base + t * P_DIM];
    g_attpart[(b * 16 + sc) * P_DIM + d] = s;
}
__global__ void k_attmean2() {
    int b = blockIdx.x >> 2, dc = blockIdx.x & 3;
    int d = dc * 128 + threadIdx.x;
    float s = 0.f;
#pragma unroll
    for (int p = 0; p < 16; p++) s += g_attpart[(b * 16 + p) * P_DIM + d];
    g_attmean[b * P_DIM + d] = s * (1.0f / (float)S_);
}
__global__ void k_pool(const float* __restrict__ outW, const float* __restrict__ outb) {
    __shared__ float am[P_DIM];
    int b = blockIdx.x, n = threadIdx.x;
    am[n] = g_attmean[b * P_DIM + n];
    __syncthreads();
    float acc = outb[n];
#pragma unroll 8
    for (int k = 0; k < P_DIM; k++) acc += am[k] * outW[k * P_DIM + n];
    g_pooled[b * P_DIM + n] = acc;
}

// ============================================================================
// Per-scale MLP heads
// ============================================================================
template <int TWOS>
__global__ void k_mlp1(const float* __restrict__ w1, const float* __restrict__ b1,
                       const float* __restrict__ gam, const float* __restrict__ bet) {
    __shared__ float pr[P_DIM];
    __shared__ float red[TWOS];
    int b = blockIdx.x, j = threadIdx.x;
    for (int k = j; k < P_DIM; k += TWOS) pr[k] = g_pooled[b * P_DIM + k];
    __syncthreads();
    float t = b1[j];
#pragma unroll 8
    for (int k = 0; k < P_DIM; k++) t += pr[k] * w1[k * TWOS + j];
    float mu = block_sum(t, red, TWOS, j) / (float)TWOS;
    float d = t - mu;
    float var = block_sum(d * d, red, TWOS, j) / (float)TWOS;
    float y = d * rsqrtf(var + EPS_) * gam[j] + bet[j];
    g_h[b * 1024 + j] = gelu_exact(y);
}

template <int TWOS, int SS, int OFF>
__global__ void k_mlp2(const float* __restrict__ w2, const float* __restrict__ b2,
                       float* __restrict__ out) {
    __shared__ float hr[TWOS];
    int b = blockIdx.x, j = threadIdx.x;
    for (int k = j; k < TWOS; k += SS) hr[k] = g_h[b * 1024 + k];
    __syncthreads();
    float acc = b2[j];
#pragma unroll 8
    for (int k = 0; k < TWOS; k++) acc += hr[k] * w2[k * SS + j];
    out[b * 896 + OFF + j] = acc;
}

// ============================================================================
// Launch
// ============================================================================
extern "C" void kernel_launch(void* const* d_in, const int* in_sizes, int n_in,
                              void* d_out, int out_size) {
    const float* X      = (const float*)d_in[0];
    const float* penta  = (const float*)d_in[1];
    const float* poss   = (const float*)d_in[2];
    const float* projW  = (const float*)d_in[3];
    const float* projb  = (const float*)d_in[4];
    const float* lng    = (const float*)d_in[5];
    const float* lnb    = (const float*)d_in[6];
    const float* qkvW   = (const float*)d_in[7];
    const float* qkvb   = (const float*)d_in[8];
    const float* outW   = (const float*)d_in[9];
    const float* outb   = (const float*)d_in[10];
    const float* w1a = (const float*)d_in[11]; const float* b1a = (const float*)d_in[12];
    const float* ga  = (const float*)d_in[13]; const float* bba = (const float*)d_in[14];
    const float* w2a = (const float*)d_in[15]; const float* b2a = (const float*)d_in[16];
    const float* w1b = (const float*)d_in[17]; const float* b1b = (const float*)d_in[18];
    const float* gb  = (const float*)d_in[19]; const float* bbb = (const float*)d_in[20];
    const float* w2b = (const float*)d_in[21]; const float* b2b = (const float*)d_in[22];
    const float* w1c = (const float*)d_in[23]; const float* b1c = (const float*)d_in[24];
    const float* gc  = (const float*)d_in[25]; const float* bbc = (const float*)d_in[26];
    const float* w2c = (const float*)d_in[27]; const float* b2c = (const float*)d_in[28];
    float* out = (float*)d_out;

    k_cent<<<NPENTA, 256>>>(penta);
    k_gemm_proj<<<dim3(P_DIM / 64, ROWS / 128), 256>>>(X, projW, projb);
    k_lgn<<<ROWS, 128>>>(lng, lnb);
    k_gemm_scores<<<dim3(NPENTA / 64, ROWS / 128), 256>>>();
    k_anchor_reduce<<<ROWS / 256, 256>>>();
    k_group<<<B_, 1024>>>();
    k_gemm_qkv<<<dim3(3 * P_DIM / 64, ROWS / 128), 256>>>(qkvW, qkvb);
    k_topk<<<B_ * NPENTA, 256>>>(poss);
    k_attng<<<dim3(B_ * NPENTA, H_), 256>>>();
    k_attmean1<<<128, 128>>>();
    k_attmean2<<<8, 128>>>();
    k_pool<<<B_, 512>>>(outW, outb);

    k_mlp1<256><<<B_, 256>>>(w1a, b1a, ga, bba);
    k_mlp2<256, 128, 0><<<B_, 128>>>(w2a, b2a, out);
    k_mlp1<512><<<B_, 512>>>(w1b, b1b, gb, bbb);
    k_mlp2<512, 256, 128><<<B_, 256>>>(w2b, b2b, out);
    k_mlp1<1024><<<B_, 1024>>>(w1c, b1c, gc, bbc);
    k_mlp2<1024, 512, 384><<<B_, 512>>>(w2c, b2c, out);
}

// round 11
// speedup vs baseline: 1.3648x; 1.1910x over previous
#include <cuda_runtime.h>
#include <math.h>

// ============================================================================
// Problem constants
// ============================================================================
#define B_     2
#define S_     2048
#define IN_DIM 1024
#define P_DIM  512
#define H_     8
#define HD_    64
#define NPENTA 1024
#define KNEI   128
#define ROWS   (B_ * S_)        // 4096
#define EPS_   1e-5f

#define PAD    20               // smem row stride (floats): 16B-aligned rows,
                                // conflict-free ldmatrix (20r mod 32 distinct spans)

// ============================================================================
// Scratch (static device globals — no runtime allocation)
// ============================================================================
__device__ float g_cent[NPENTA * P_DIM];
__device__ float g_zpre[ROWS * P_DIM];
__device__ float g_zh[ROWS * P_DIM];              // z pre-split (written by k_lgn)
__device__ float g_zl[ROWS * P_DIM];
__device__ float g_pval[ROWS * 16];
__device__ int   g_pidx[ROWS * 16];
__device__ int   g_anchor[ROWS];
__device__ int   g_routes[B_ * NPENTA * KNEI];
__device__ float g_qkv[ROWS * 3 * P_DIM];
__device__ float g_att[ROWS * P_DIM];
__device__ float g_attpart[B_ * 16 * P_DIM];
__device__ float g_attmean[B_ * P_DIM];
__device__ float g_pooled[B_ * P_DIM];
__device__ float g_h[B_ * 1024];

// ============================================================================
// Helpers
// ============================================================================
__device__ __forceinline__ float gelu_exact(float x) {
    return 0.5f * x * (1.0f + erff(x * 0.70710678118654752440f));
}

__device__ __forceinline__ float block_sum(float v, float* red, int n, int tid) {
    red[tid] = v;
    __syncthreads();
    for (int s = n >> 1; s > 0; s >>= 1) {
        if (tid < s) red[tid] += red[tid + s];
        __syncthreads();
    }
    float r = red[0];
    __syncthreads();
    return r;
}

__device__ __forceinline__ float warp_sum(float v) {
#pragma unroll
    for (int o = 16; o; o >>= 1) v += __shfl_xor_sync(0xffffffffu, v, o);
    return v;
}

__device__ __forceinline__ unsigned cvt_tf32(float x) {
    unsigned r;
    asm("cvt.rna.tf32.f32 %0, %1;" : "=r"(r) : "f"(x));
    return r;
}

__device__ __forceinline__ void split1(float x, float& h, float& l) {
    h = __uint_as_float(cvt_tf32(x));
    l = __uint_as_float(cvt_tf32(x - h));
}

__device__ __forceinline__ void split4(const float4& v, float4& h, float4& l) {
    split1(v.x, h.x, l.x);
    split1(v.y, h.y, l.y);
    split1(v.z, h.z, l.z);
    split1(v.w, h.w, l.w);
}

__device__ __forceinline__ void mma_tf32(float* c, const unsigned* a, const unsigned* b) {
    asm volatile(
        "mma.sync.aligned.m16n8k8.row.col.f32.tf32.tf32.f32 "
        "{%0,%1,%2,%3}, {%4,%5,%6,%7}, {%8,%9}, {%0,%1,%2,%3};"
        : "+f"(c[0]), "+f"(c[1]), "+f"(c[2]), "+f"(c[3])
        : "r"(a[0]), "r"(a[1]), "r"(a[2]), "r"(a[3]), "r"(b[0]), "r"(b[1]));
}

__device__ __forceinline__ void ldsm4(unsigned* r, unsigned saddr) {
    asm volatile(
        "ldmatrix.sync.aligned.m8n8.x4.shared.b16 {%0,%1,%2,%3}, [%4];"
        : "=r"(r[0]), "=r"(r[1]), "=r"(r[2]), "=r"(r[3]) : "r"(saddr));
}

// ============================================================================
// centroids = normalize(mean over 5 vertices)
// ============================================================================
__global__ void k_cent(const float* __restrict__ penta) {
    __shared__ float red[256];
    int p = blockIdx.x, tid = threadIdx.x;
    float v[2];
    float ss = 0.f;
#pragma unroll
    for (int r = 0; r < 2; r++) {
        int d = tid + r * 256;
        float s = 0.f;
#pragma unroll
        for (int i = 0; i < 5; i++) s += penta[(p * 5 + i) * P_DIM + d];
        v[r] = s / 5.0f;
        ss += v[r] * v[r];
    }
    float tot = block_sum(ss, red, 256, tid);
    float den = fmaxf(sqrtf(tot), 1e-12f);
#pragma unroll
    for (int r = 0; r < 2; r++) g_cent[p * P_DIM + tid + r * 256] = v[r] / den;
}

// ============================================================================
// 3xTF32 tensor-core GEMM, hi/lo in smem, ldmatrix fragments (839us R8 body).
// PSA: A operand arrives PRE-SPLIT in global (Ahg/Alg) — skip A-side split.
// C[M,N] = A[M,K] @ B (+bias). TB: B stored [N,K].
// BM=128, BN=64, BK=16, 256 threads = 8 warps (4m x 2n), warp tile 32x32.
// ============================================================================
template <int N, int K, bool TB, bool BIAS, bool ARGMAX, bool PSA>
__device__ __forceinline__ void mma_gemm_body(const float* __restrict__ A,
                                              const float* __restrict__ Alg,
                                              const float* __restrict__ Bm,
                                              const float* __restrict__ bias,
                                              float* __restrict__ C) {
    __shared__ float Ah[2][128][PAD];
    __shared__ float Al[2][128][PAD];
    __shared__ float Bh[2][64][PAD];
    __shared__ float Bl[2][64][PAD];

    const int tid  = threadIdx.x;
    const int lane = tid & 31;
    const int warp = tid >> 5;
    const int wm = warp >> 1, wn = warp & 1;
    const int row0 = blockIdx.y * 128, col0 = blockIdx.x * 64;

    // global-load mappings (exact R8)
    const int ar = tid >> 2;            // A rows 0..63 (+64)
    const int ac = (tid & 3) * 4;       // A k-offset
    const int bk = tid >> 4;            // !TB: B row (k) 0..15
    const int bn = (tid & 15) * 4;      //      B col (n)
    const int tn = tid >> 2;            //  TB: B row (n) 0..63
    const int tk = (tid & 3) * 4;       //      B col (k)

    float acc[2][4][4];
#pragma unroll
    for (int mt = 0; mt < 2; mt++)
#pragma unroll
        for (int nt = 0; nt < 4; nt++)
#pragma unroll
            for (int r = 0; r < 4; r++) acc[mt][nt][r] = 0.f;

    const unsigned offA = ((unsigned)(wm * 32 + (lane & 15)) * PAD + (unsigned)((lane >> 4) * 4)) * 4u;
    const int brow = (lane & 7) + ((lane >> 4) << 3);
    const int bcol = ((lane >> 3) & 1) * 4;
    const unsigned offB = ((unsigned)(wn * 32 + brow) * PAD + (unsigned)bcol) * 4u;
    const unsigned baseAh = (unsigned)__cvta_generic_to_shared(&Ah[0][0][0]);
    const unsigned baseAl = (unsigned)__cvta_generic_to_shared(&Al[0][0][0]);
    const unsigned baseBh = (unsigned)__cvta_generic_to_shared(&Bh[0][0][0]);
    const unsigned baseBl = (unsigned)__cvta_generic_to_shared(&Bl[0][0][0]);
    const unsigned A_TILE = 128u * PAD * 4u;
    const unsigned B_TILE = 64u * PAD * 4u;
    const unsigned MT_OFF = 16u * PAD * 4u;

    float4 a0v, a1v, a0l, a1l, bvv;

    // ---- stage 0 global loads
    a0v = *(const float4*)(A + (size_t)(row0 + ar) * K + ac);
    a1v = *(const float4*)(A + (size_t)(row0 + ar + 64) * K + ac);
    if (PSA) {
        a0l = *(const float4*)(Alg + (size_t)(row0 + ar) * K + ac);
        a1l = *(const float4*)(Alg + (size_t)(row0 + ar + 64) * K + ac);
    }
    if (!TB) bvv = *(const float4*)(Bm + (size_t)bk * N + col0 + bn);
    else     bvv = *(const float4*)(Bm + (size_t)(col0 + tn) * K + tk);

    // ---- split (if needed) + float4 store stage 0
    {
        if (PSA) {
            *(float4*)&Ah[0][ar][ac] = a0v;      *(float4*)&Al[0][ar][ac] = a0l;
            *(float4*)&Ah[0][ar + 64][ac] = a1v; *(float4*)&Al[0][ar + 64][ac] = a1l;
        } else {
            float4 h, l;
            split4(a0v, h, l);
            *(float4*)&Ah[0][ar][ac] = h;      *(float4*)&Al[0][ar][ac] = l;
            split4(a1v, h, l);
            *(float4*)&Ah[0][ar + 64][ac] = h; *(float4*)&Al[0][ar + 64][ac] = l;
        }
        if (!TB) {
            float hb, lb;
            split1(bvv.x, hb, lb); Bh[0][bn + 0][bk] = hb; Bl[0][bn + 0][bk] = lb;
            split1(bvv.y, hb, lb); Bh[0][bn + 1][bk] = hb; Bl[0][bn + 1][bk] = lb;
            split1(bvv.z, hb, lb); Bh[0][bn + 2][bk] = hb; Bl[0][bn + 2][bk] = lb;
            split1(bvv.w, hb, lb); Bh[0][bn + 3][bk] = hb; Bl[0][bn + 3][bk] = lb;
        } else {
            float4 h2, l2;
            split4(bvv, h2, l2);
            *(float4*)&Bh[0][tn][tk] = h2;  *(float4*)&Bl[0][tn][tk] = l2;
        }
    }
    __syncthreads();

    int buf = 0;
    for (int k0 = 16; k0 < K + 16; k0 += 16) {
        if (k0 < K) {
            a0v = *(const float4*)(A + (size_t)(row0 + ar) * K + k0 + ac);
            a1v = *(const float4*)(A + (size_t)(row0 + ar + 64) * K + k0 + ac);
            if (PSA) {
                a0l = *(const float4*)(Alg + (size_t)(row0 + ar) * K + k0 + ac);
                a1l = *(const float4*)(Alg + (size_t)(row0 + ar + 64) * K + k0 + ac);
            }
            if (!TB) bvv = *(const float4*)(Bm + (size_t)(k0 + bk) * N + col0 + bn);
            else     bvv = *(const float4*)(Bm + (size_t)(col0 + tn) * K + k0 + tk);
        }
        // ---- compute on buf
        const unsigned aSt = (unsigned)buf * A_TILE;
        const unsigned bSt = (unsigned)buf * B_TILE;
#pragma unroll
        for (int kc = 0; kc < 2; kc++) {
            unsigned ah[2][4], alr[2][4], bh[2][4], blr[2][4];
#pragma unroll
            for (int mt = 0; mt < 2; mt++) {
                unsigned ad = aSt + offA + (unsigned)mt * MT_OFF + (unsigned)(kc * 32);
                ldsm4(ah[mt],  baseAh + ad);
                ldsm4(alr[mt], baseAl + ad);
            }
#pragma unroll
            for (int np = 0; np < 2; np++) {
                unsigned bd = bSt + offB + (unsigned)np * MT_OFF + (unsigned)(kc * 32);
                ldsm4(bh[np],  baseBh + bd);
                ldsm4(blr[np], baseBl + bd);
            }
#pragma unroll
            for (int mt = 0; mt < 2; mt++)
#pragma unroll
                for (int np = 0; np < 2; np++)
#pragma unroll
                    for (int hf = 0; hf < 2; hf++) {
                        float* c = acc[mt][np * 2 + hf];
                        mma_tf32(c, ah[mt],  &bh[np][hf * 2]);
                        mma_tf32(c, alr[mt], &bh[np][hf * 2]);
                        mma_tf32(c, ah[mt],  &blr[np][hf * 2]);
                    }
        }
        // ---- split + store next stage
        if (k0 < K) {
            const int nb = buf ^ 1;
            if (PSA) {
                *(float4*)&Ah[nb][ar][ac] = a0v;      *(float4*)&Al[nb][ar][ac] = a0l;
                *(float4*)&Ah[nb][ar + 64][ac] = a1v; *(float4*)&Al[nb][ar + 64][ac] = a1l;
            } else {
                float4 h, l;
                split4(a0v, h, l);
                *(float4*)&Ah[nb][ar][ac] = h;      *(float4*)&Al[nb][ar][ac] = l;
                split4(a1v, h, l);
                *(float4*)&Ah[nb][ar + 64][ac] = h; *(float4*)&Al[nb][ar + 64][ac] = l;
            }
            if (!TB) {
                float hb, lb;
                split1(bvv.x, hb, lb); Bh[nb][bn + 0][bk] = hb; Bl[nb][bn + 0][bk] = lb;
                split1(bvv.y, hb, lb); Bh[nb][bn + 1][bk] = hb; Bl[nb][bn + 1][bk] = lb;
                split1(bvv.z, hb, lb); Bh[nb][bn + 2][bk] = hb; Bl[nb][bn + 2][bk] = lb;
                split1(bvv.w, hb, lb); Bh[nb][bn + 3][bk] = hb; Bl[nb][bn + 3][bk] = lb;
            } else {
                float4 h2, l2;
                split4(bvv, h2, l2);
                *(float4*)&Bh[nb][tn][tk] = h2;  *(float4*)&Bl[nb][tn][tk] = l2;
            }
        }
        __syncthreads();
        buf ^= 1;
    }

    if constexpr (ARGMAX) {
        __shared__ float s_v[128][2];
        __shared__ int   s_c[128][2];
#pragma unroll
        for (int mt = 0; mt < 2; mt++) {
#pragma unroll
            for (int half = 0; half < 2; half++) {
                const int rloc = wm * 32 + mt * 16 + (lane >> 2) + half * 8;
                float best = -1e30f;
                int bc = 0;
#pragma unroll
                for (int nt = 0; nt < 4; nt++) {
                    const int cl = wn * 32 + nt * 8 + (lane & 3) * 2;
                    float v0 = acc[mt][nt][half * 2];
                    float v1 = acc[mt][nt][half * 2 + 1];
                    if (v0 > best) { best = v0; bc = cl; }
                    if (v1 > best) { best = v1; bc = cl + 1; }
                }
#pragma unroll
                for (int o = 1; o < 4; o <<= 1) {
                    float ov = __shfl_xor_sync(0xffffffffu, best, o);
                    int   oc = __shfl_xor_sync(0xffffffffu, bc, o);
                    if (ov > best || (ov == best && oc < bc)) { best = ov; bc = oc; }
                }
                if ((lane & 3) == 0) { s_v[rloc][wn] = best; s_c[rloc][wn] = bc; }
            }
        }
        __syncthreads();
        if (tid < 128) {
            float best = s_v[tid][0];
            int bc = s_c[tid][0];
            if (s_v[tid][1] > best) { best = s_v[tid][1]; bc = s_c[tid][1]; }
            g_pval[(size_t)(row0 + tid) * 16 + blockIdx.x] = best;
            g_pidx[(size_t)(row0 + tid) * 16 + blockIdx.x] = col0 + bc;
        }
    } else {
#pragma unroll
        for (int mt = 0; mt < 2; mt++) {
            const int r0 = row0 + wm * 32 + mt * 16 + (lane >> 2);
#pragma unroll
            for (int nt = 0; nt < 4; nt++) {
                const int cc = col0 + wn * 32 + nt * 8 + (lane & 3) * 2;
                float b0 = 0.f, b1 = 0.f;
                if (BIAS) { b0 = bias[cc]; b1 = bias[cc + 1]; }
                float2* p0 = (float2*)&C[(size_t)r0 * N + cc];
                float2* p1 = (float2*)&C[(size_t)(r0 + 8) * N + cc];
                *p0 = make_float2(acc[mt][nt][0] + b0, acc[mt][nt][1] + b1);
                *p1 = make_float2(acc[mt][nt][2] + b0, acc[mt][nt][3] + b1);
            }
        }
    }
}

__global__ void __launch_bounds__(256)
k_gemm_proj(const float* __restrict__ X, const float* __restrict__ W,
            const float* __restrict__ b) {
    mma_gemm_body<P_DIM, IN_DIM, false, true, false, false>(X, nullptr, W, b, g_zpre);
}
__global__ void __launch_bounds__(256) k_gemm_scores() {
    mma_gemm_body<NPENTA, P_DIM, true, false, true, true>(g_zh, g_zl, g_cent, nullptr, nullptr);
}
__global__ void __launch_bounds__(256)
k_gemm_qkv(const float* __restrict__ W, const float* __restrict__ b) {
    mma_gemm_body<3 * P_DIM, P_DIM, false, true, false, true>(g_zh, g_zl, W, b, g_qkv);
}

// ============================================================================
// LayerNorm + GELU + L2-normalize per row (512) -> writes z PRE-SPLIT (hi/lo)
// ============================================================================
__global__ void __launch_bounds__(128)
k_lgn(const float* __restrict__ gam, const float* __restrict__ bet) {
    __shared__ float wred[4];
    int row = blockIdx.x, tid = threadIdx.x;
    int lane = tid & 31, warp = tid >> 5;
    const float4* src = (const float4*)(g_zpre + (size_t)row * P_DIM);
    float4 x = src[tid];
    float s = warp_sum(x.x + x.y + x.z + x.w);
    if (lane == 0) wred[warp] = s;
    __syncthreads();
    float mu = (wred[0] + wred[1] + wred[2] + wred[3]) * (1.0f / 512.0f);
    __syncthreads();
    float4 d = make_float4(x.x - mu, x.y - mu, x.z - mu, x.w - mu);
    s = warp_sum(d.x * d.x + d.y * d.y + d.z * d.z + d.w * d.w);
    if (lane == 0) wred[warp] = s;
    __syncthreads();
    float var = (wred[0] + wred[1] + wred[2] + wred[3]) * (1.0f / 512.0f);
    __syncthreads();
    float rs = rsqrtf(var + EPS_);
    float4 gv = ((const float4*)gam)[tid];
    float4 bv = ((const float4*)bet)[tid];
    float4 hh;
    hh.x = gelu_exact(d.x * rs * gv.x + bv.x);
    hh.y = gelu_exact(d.y * rs * gv.y + bv.y);
    hh.z = gelu_exact(d.z * rs * gv.z + bv.z);
    hh.w = gelu_exact(d.w * rs * gv.w + bv.w);
    s = warp_sum(hh.x * hh.x + hh.y * hh.y + hh.z * hh.z + hh.w * hh.w);
    if (lane == 0) wred[warp] = s;
    __syncthreads();
    float nrm = sqrtf(wred[0] + wred[1] + wred[2] + wred[3]);
    float inv = 1.0f / fmaxf(nrm, 1e-12f);
    float4 z = make_float4(hh.x * inv, hh.y * inv, hh.z * inv, hh.w * inv);
    float4 zh, zl;
    split4(z, zh, zl);
    ((float4*)(g_zh + (size_t)row * P_DIM))[tid] = zh;
    ((float4*)(g_zl + (size_t)row * P_DIM))[tid] = zl;
}

// ============================================================================
// Combine 16 col-block argmax partials (ascending, strict > = first index)
// ============================================================================
__global__ void k_anchor_reduce() {
    int row = blockIdx.x * 256 + threadIdx.x;
    if (row >= ROWS) return;
    float best = g_pval[(size_t)row * 16];
    int bi = g_pidx[(size_t)row * 16];
#pragma unroll
    for (int c = 1; c < 16; c++) {
        float v = g_pval[(size_t)row * 16 + c];
        if (v > best) { best = v; bi = g_pidx[(size_t)row * 16 + c]; }
    }
    g_anchor[row] = bi;
}

// ============================================================================
// Exact 128-NN per (batch, anchor) via histogram select on key
// (dist_bits<<32)|idx — same set as jax top_k(-dist) incl. tie-breaks.
// ============================================================================
__global__ void __launch_bounds__(256) k_topk(const float* __restrict__ positions) {
    __shared__ unsigned int db[S_];
    __shared__ unsigned int hist[2048];
    __shared__ unsigned long long cand[S_];
    __shared__ int scan[256];
    __shared__ int sb[4];
    int blk = blockIdx.x;
    int b = blk >> 10;
    int a = blk & 1023;
    int tid = threadIdx.x;
    if (tid == 0) { sb[2] = 0; sb[3] = 0; }
    float pq = positions[a];
    for (int i = tid; i < 2048; i += 256) hist[i] = 0;
    __syncthreads();
    for (int i = tid; i < S_; i += 256) {
        float p = positions[g_anchor[b * S_ + i]];
        unsigned int u = __float_as_uint(fabsf(pq - p));
        db[i] = u;
        atomicAdd(&hist[u >> 21], 1u);
    }
    __syncthreads();
    int base = tid * 8;
    unsigned int c[8];
    int loc = 0;
#pragma unroll
    for (int j = 0; j < 8; j++) { c[j] = hist[base + j]; loc += (int)c[j]; }
    int v = loc;
    scan[tid] = v;
    __syncthreads();
    for (int off = 1; off < 256; off <<= 1) {
        int t = (tid >= off) ? scan[tid - off] : 0;
        __syncthreads();
        v += t;
        scan[tid] = v;
        __syncthreads();
    }
    int run = v - loc;
#pragma unroll
    for (int j = 0; j < 8; j++) {
        int cnt = (int)c[j];
        if (run < KNEI && run + cnt >= KNEI) { sb[0] = base + j; sb[1] = run; }
        run += cnt;
    }
    __syncthreads();
    unsigned int bstar = (unsigned int)sb[0];
    int c0 = sb[1];
    int out = blk * KNEI;
    for (int i = tid; i < S_; i += 256) {
        unsigned int bkt = db[i] >> 21;
        if (bkt < bstar) {
            int s2 = atomicAdd(&sb[2], 1);
            g_routes[out + s2] = i;
        } else if (bkt == bstar) {
            int cp = atomicAdd(&sb[3], 1);
            cand[cp] = ((unsigned long long)db[i] << 32) | (unsigned int)i;
        }
    }
    __syncthreads();
    int ncand = sb[3];
    int need = KNEI - c0;
    int P = 1;
    while (P < ncand) P <<= 1;
    if (P < 2) P = 2;
    for (int i = ncand + tid; i < P; i += 256) cand[i] = 0xFFFFFFFFFFFFFFFFull;
    __syncthreads();
    for (int len = 2; len <= P; len <<= 1) {
        for (int j = len >> 1; j > 0; j >>= 1) {
            for (int i = tid; i < P; i += 256) {
                int p = i ^ j;
                if (p > i) {
                    bool up = ((i & len) == 0);
                    unsigned long long x = cand[i], y = cand[p];
                    if ((x > y) == up) { cand[i] = y; cand[p] = x; }
                }
            }
            __syncthreads();
        }
    }
    for (int r = tid; r < need; r += 256) g_routes[out + c0 + r] = (int)(cand[r] & 0xffffffffu);
}

// ============================================================================
// Gathered attention: block per (b,q); warp per head, barrier-free mainloop.
// (exact 839us version)
// ============================================================================
__global__ void __launch_bounds__(256) k_attention() {
    __shared__ int   rbase[KNEI];
    __shared__ float sc[H_][KNEI];
    int row = blockIdx.x;
    int b = row >> 11;
    int tid = threadIdx.x;
    int warp = tid >> 5, lane = tid & 31;
    int anc = g_anchor[row];
    if (tid < KNEI)
        rbase[tid] = (b * S_ + g_routes[((b << 10) + anc) * KNEI + tid]) * (3 * P_DIM);
    __syncthreads();

    const int h = warp;
    const int hoff = h * HD_;
    const size_t qrow = (size_t)row * (3 * P_DIM);
    const int qd = (lane & 7) * 8;
    const int ng = lane >> 3;

    float4 q0 = *(const float4*)&g_qkv[qrow + hoff + qd];
    float4 q1 = *(const float4*)&g_qkv[qrow + hoff + qd + 4];

#pragma unroll 4
    for (int rep = 0; rep < 32; rep++) {
        int n = rep * 4 + ng;
        const float* kr = &g_qkv[(size_t)rbase[n] + P_DIM + hoff + qd];
        float4 k0 = *(const float4*)kr;
        float4 k1 = *(const float4*)(kr + 4);
        float s = q0.x * k0.x + q0.y * k0.y + q0.z * k0.z + q0.w * k0.w
                + q1.x * k1.x + q1.y * k1.y + q1.z * k1.z + q1.w * k1.w;
        s += __shfl_xor_sync(0xffffffffu, s, 4);
        s += __shfl_xor_sync(0xffffffffu, s, 2);
        s += __shfl_xor_sync(0xffffffffu, s, 1);
        if ((lane & 7) == 0) sc[h][n] = s * 0.125f;
    }
    __syncwarp();

    float v0 = sc[h][lane], v1 = sc[h][lane + 32];
    float v2 = sc[h][lane + 64], v3 = sc[h][lane + 96];
    float m = fmaxf(fmaxf(v0, v1), fmaxf(v2, v3));
#pragma unroll
    for (int o = 16; o; o >>= 1) m = fmaxf(m, __shfl_xor_sync(0xffffffffu, m, o));
    v0 = expf(v0 - m); v1 = expf(v1 - m); v2 = expf(v2 - m); v3 = expf(v3 - m);
    float ssum = warp_sum(v0 + v1 + v2 + v3);
    float inv = 1.0f / ssum;
    sc[h][lane] = v0; sc[h][lane + 32] = v1;
    sc[h][lane + 64] = v2; sc[h][lane + 96] = v3;
    __syncwarp();

    float2 acc = make_float2(0.f, 0.f);
    const int d2 = lane * 2;
#pragma unroll 4
    for (int i = 0; i < KNEI; i++) {
        float p = sc[h][i];
        float2 vv = *(const float2*)&g_qkv[(size_t)rbase[i] + 2 * P_DIM + hoff + d2];
        acc.x += p * vv.x;
        acc.y += p * vv.y;
    }
    float* dst = &g_att[(size_t)row * P_DIM + hoff + d2];
    dst[0] = acc.x * inv;
    dst[1] = acc.y * inv;
}

// ============================================================================
// Pooling + out projection folded after the mean
// ============================================================================
__global__ void k_attmean1() {
    int bb = blockIdx.x;
    int b  = bb >> 6;
    int dc = (bb >> 4) & 3;
    int sc = bb & 15;
    int d = dc * 128 + threadIdx.x;
    float s = 0.f;
    int base = (b * S_ + sc * 128) * P_DIM + d;
    for (int t = 0; t < 128; t++) s += g_att[base + t * P_DIM];
    g_attpart[(b * 16 + sc) * P_DIM + d] = s;
}
__global__ void k_attmean2() {
    int b = blockIdx.x >> 2, dc = blockIdx.x & 3;
    int d = dc * 128 + threadIdx.x;
    float s = 0.f;
#pragma unroll
    for (int p = 0; p < 16; p++) s += g_attpart[(b * 16 + p) * P_DIM + d];
    g_attmean[b * P_DIM + d] = s * (1.0f / (float)S_);
}
__global__ void k_pool(const float* __restrict__ outW, const float* __restrict__ outb) {
    __shared__ float am[P_DIM];
    int b = blockIdx.x, n = threadIdx.x;
    am[n] = g_attmean[b * P_DIM + n];
    __syncthreads();
    float acc = outb[n];
#pragma unroll 8
    for (int k = 0; k < P_DIM; k++) acc += am[k] * outW[k * P_DIM + n];
    g_pooled[b * P_DIM + n] = acc;
}

// ============================================================================
// Per-scale MLP heads
// ============================================================================
template <int TWOS>
__global__ void k_mlp1(const float* __restrict__ w1, const float* __restrict__ b1,
                       const float* __restrict__ gam, const float* __restrict__ bet) {
    __shared__ float pr[P_DIM];
    __shared__ float red[TWOS];
    int b = blockIdx.x, j = threadIdx.x;
    for (int k = j; k < P_DIM; k += TWOS) pr[k] = g_pooled[b * P_DIM + k];
    __syncthreads();
    float t = b1[j];
#pragma unroll 8
    for (int k = 0; k < P_DIM; k++) t += pr[k] * w1[k * TWOS + j];
    float mu = block_sum(t, red, TWOS, j) / (float)TWOS;
    float d = t - mu;
    float var = block_sum(d * d, red, TWOS, j) / (float)TWOS;
    float y = d * rsqrtf(var + EPS_) * gam[j] + bet[j];
    g_h[b * 1024 + j] = gelu_exact(y);
}

template <int TWOS, int SS, int OFF>
__global__ void k_mlp2(const float* __restrict__ w2, const float* __restrict__ b2,
                       float* __restrict__ out) {
    __shared__ float hr[TWOS];
    int b = blockIdx.x, j = threadIdx.x;
    for (int k = j; k < TWOS; k += SS) hr[k] = g_h[b * 1024 + k];
    __syncthreads();
    float acc = b2[j];
#pragma unroll 8
    for (int k = 0; k < TWOS; k++) acc += hr[k] * w2[k * SS + j];
    out[b * 896 + OFF + j] = acc;
}

// ============================================================================
// Launch
// ============================================================================
extern "C" void kernel_launch(void* const* d_in, const int* in_sizes, int n_in,
                              void* d_out, int out_size) {
    const float* X      = (const float*)d_in[0];
    const float* penta  = (const float*)d_in[1];
    const float* poss   = (const float*)d_in[2];
    const float* projW  = (const float*)d_in[3];
    const float* projb  = (const float*)d_in[4];
    const float* lng    = (const float*)d_in[5];
    const float* lnb    = (const float*)d_in[6];
    const float* qkvW   = (const float*)d_in[7];
    const float* qkvb   = (const float*)d_in[8];
    const float* outW   = (const float*)d_in[9];
    const float* outb   = (const float*)d_in[10];
    const float* w1a = (const float*)d_in[11]; const float* b1a = (const float*)d_in[12];
    const float* ga  = (const float*)d_in[13]; const float* bba = (const float*)d_in[14];
    const float* w2a = (const float*)d_in[15]; const float* b2a = (const float*)d_in[16];
    const float* w1b = (const float*)d_in[17]; const float* b1b = (const float*)d_in[18];
    const float* gb  = (const float*)d_in[19]; const float* bbb = (const float*)d_in[20];
    const float* w2b = (const float*)d_in[21]; const float* b2b = (const float*)d_in[22];
    const float* w1c = (const float*)d_in[23]; const float* b1c = (const float*)d_in[24];
    const float* gc  = (const float*)d_in[25]; const float* bbc = (const float*)d_in[26];
    const float* w2c = (const float*)d_in[27]; const float* b2c = (const float*)d_in[28];
    float* out = (float*)d_out;

    k_cent<<<NPENTA, 256>>>(penta);
    k_gemm_proj<<<dim3(P_DIM / 64, ROWS / 128), 256>>>(X, projW, projb);
    k_lgn<<<ROWS, 128>>>(lng, lnb);
    k_gemm_scores<<<dim3(NPENTA / 64, ROWS / 128), 256>>>();
    k_anchor_reduce<<<ROWS / 256, 256>>>();
    k_gemm_qkv<<<dim3(3 * P_DIM / 64, ROWS / 128), 256>>>(qkvW, qkvb);
    k_topk<<<B_ * NPENTA, 256>>>(poss);
    k_attention<<<ROWS, 256>>>();
    k_attmean1<<<128, 128>>>();
    k_attmean2<<<8, 128>>>();
    k_pool<<<B_, 512>>>(outW, outb);

    k_mlp1<256><<<B_, 256>>>(w1a, b1a, ga, bba);
    k_mlp2<256, 128, 0><<<B_, 128>>>(w2a, b2a, out);
    k_mlp1<512><<<B_, 512>>>(w1b, b1b, gb, bbb);
    k_mlp2<512, 256, 128><<<B_, 256>>>(w2b, b2b, out);
    k_mlp1<1024><<<B_, 1024>>>(w1c, b1c, gc, bbc);
    k_mlp2<1024, 512, 384><<<B_, 512>>>(w2c, b2c, out);
}

// round 12
// speedup vs baseline: 1.4551x; 1.0661x over previous
#include <cuda_runtime.h>
#include <cuda_bf16.h>
#include <math.h>

// ============================================================================
// Problem constants
// ============================================================================
#define B_     2
#define S_     2048
#define IN_DIM 1024
#define P_DIM  512
#define H_     8
#define HD_    64
#define NPENTA 1024
#define KNEI   128
#define ROWS   (B_ * S_)        // 4096
#define EPS_   1e-5f

#define PAD    20               // smem row stride (floats): 16B-aligned rows,
                                // conflict-free ldmatrix (20r mod 32 distinct spans)

// ============================================================================
// Scratch (static device globals — no runtime allocation)
// ============================================================================
__device__ float g_cent[NPENTA * P_DIM];
__device__ float g_zpre[ROWS * P_DIM];
__device__ float g_z[ROWS * P_DIM];
__device__ float g_pval[ROWS * 16];
__device__ int   g_pidx[ROWS * 16];
__device__ int   g_anchor[ROWS];
__device__ int   g_routes[B_ * NPENTA * KNEI];
__device__ float g_qkv[ROWS * 3 * P_DIM];
__device__ __nv_bfloat16 g_kvh[ROWS * 2 * P_DIM];  // bf16 K|V (halved attn traffic)
__device__ float g_att[ROWS * P_DIM];
__device__ float g_attpart[B_ * 16 * P_DIM];
__device__ float g_attmean[B_ * P_DIM];
__device__ float g_pooled[B_ * P_DIM];
__device__ float g_h[B_ * 1024];

// ============================================================================
// Helpers
// ============================================================================
__device__ __forceinline__ float gelu_exact(float x) {
    return 0.5f * x * (1.0f + erff(x * 0.70710678118654752440f));
}

__device__ __forceinline__ float block_sum(float v, float* red, int n, int tid) {
    red[tid] = v;
    __syncthreads();
    for (int s = n >> 1; s > 0; s >>= 1) {
        if (tid < s) red[tid] += red[tid + s];
        __syncthreads();
    }
    float r = red[0];
    __syncthreads();
    return r;
}

__device__ __forceinline__ float warp_sum(float v) {
#pragma unroll
    for (int o = 16; o; o >>= 1) v += __shfl_xor_sync(0xffffffffu, v, o);
    return v;
}

__device__ __forceinline__ unsigned cvt_tf32(float x) {
    unsigned r;
    asm("cvt.rna.tf32.f32 %0, %1;" : "=r"(r) : "f"(x));
    return r;
}

__device__ __forceinline__ void split1(float x, float& h, float& l) {
    h = __uint_as_float(cvt_tf32(x));
    l = __uint_as_float(cvt_tf32(x - h));
}

__device__ __forceinline__ void split4(const float4& v, float4& h, float4& l) {
    split1(v.x, h.x, l.x);
    split1(v.y, h.y, l.y);
    split1(v.z, h.z, l.z);
    split1(v.w, h.w, l.w);
}

__device__ __forceinline__ void mma_tf32(float* c, const unsigned* a, const unsigned* b) {
    asm volatile(
        "mma.sync.aligned.m16n8k8.row.col.f32.tf32.tf32.f32 "
        "{%0,%1,%2,%3}, {%4,%5,%6,%7}, {%8,%9}, {%0,%1,%2,%3};"
        : "+f"(c[0]), "+f"(c[1]), "+f"(c[2]), "+f"(c[3])
        : "r"(a[0]), "r"(a[1]), "r"(a[2]), "r"(a[3]), "r"(b[0]), "r"(b[1]));
}

__device__ __forceinline__ void ldsm4(unsigned* r, unsigned saddr) {
    asm volatile(
        "ldmatrix.sync.aligned.m8n8.x4.shared.b16 {%0,%1,%2,%3}, [%4];"
        : "=r"(r[0]), "=r"(r[1]), "=r"(r[2]), "=r"(r[3]) : "r"(saddr));
}

// ============================================================================
// centroids = normalize(mean over 5 vertices)
// ============================================================================
__global__ void k_cent(const float* __restrict__ penta) {
    __shared__ float red[256];
    int p = blockIdx.x, tid = threadIdx.x;
    float v[2];
    float ss = 0.f;
#pragma unroll
    for (int r = 0; r < 2; r++) {
        int d = tid + r * 256;
        float s = 0.f;
#pragma unroll
        for (int i = 0; i < 5; i++) s += penta[(p * 5 + i) * P_DIM + d];
        v[r] = s / 5.0f;
        ss += v[r] * v[r];
    }
    float tot = block_sum(ss, red, 256, tid);
    float den = fmaxf(sqrtf(tot), 1e-12f);
#pragma unroll
    for (int r = 0; r < 2; r++) g_cent[p * P_DIM + tid + r * 256] = v[r] / den;
}

// ============================================================================
// 3xTF32 tensor-core GEMM, hi/lo split in-kernel into smem, ldmatrix
// fragments. EXACT R8 (839us) body. KVH: epilogue also writes bf16 copy of
// columns >= P_DIM (the K|V planes) to g_kvh.
// ============================================================================
template <int N, int K, bool TB, bool BIAS, bool ARGMAX, bool KVH>
__device__ __forceinline__ void mma_gemm_body(const float* __restrict__ A,
                                              const float* __restrict__ Bm,
                                              const float* __restrict__ bias,
                                              float* __restrict__ C) {
    __shared__ float Ah[2][128][PAD];
    __shared__ float Al[2][128][PAD];
    __shared__ float Bh[2][64][PAD];
    __shared__ float Bl[2][64][PAD];

    const int tid  = threadIdx.x;
    const int lane = tid & 31;
    const int warp = tid >> 5;
    const int wm = warp >> 1, wn = warp & 1;
    const int row0 = blockIdx.y * 128, col0 = blockIdx.x * 64;

    // global-load mappings (exact R8)
    const int ar = tid >> 2;            // A rows 0..63 (+64)
    const int ac = (tid & 3) * 4;       // A k-offset
    const int bk = tid >> 4;            // !TB: B row (k) 0..15
    const int bn = (tid & 15) * 4;      //      B col (n)
    const int tn = tid >> 2;            //  TB: B row (n) 0..63
    const int tk = (tid & 3) * 4;       //      B col (k)

    float acc[2][4][4];
#pragma unroll
    for (int mt = 0; mt < 2; mt++)
#pragma unroll
        for (int nt = 0; nt < 4; nt++)
#pragma unroll
            for (int r = 0; r < 4; r++) acc[mt][nt][r] = 0.f;

    const unsigned offA = ((unsigned)(wm * 32 + (lane & 15)) * PAD + (unsigned)((lane >> 4) * 4)) * 4u;
    const int brow = (lane & 7) + ((lane >> 4) << 3);
    const int bcol = ((lane >> 3) & 1) * 4;
    const unsigned offB = ((unsigned)(wn * 32 + brow) * PAD + (unsigned)bcol) * 4u;
    const unsigned baseAh = (unsigned)__cvta_generic_to_shared(&Ah[0][0][0]);
    const unsigned baseAl = (unsigned)__cvta_generic_to_shared(&Al[0][0][0]);
    const unsigned baseBh = (unsigned)__cvta_generic_to_shared(&Bh[0][0][0]);
    const unsigned baseBl = (unsigned)__cvta_generic_to_shared(&Bl[0][0][0]);
    const unsigned A_TILE = 128u * PAD * 4u;
    const unsigned B_TILE = 64u * PAD * 4u;
    const unsigned MT_OFF = 16u * PAD * 4u;

    float4 a0v, a1v, bvv;

    // ---- stage 0 global loads
    a0v = *(const float4*)(A + (size_t)(row0 + ar) * K + ac);
    a1v = *(const float4*)(A + (size_t)(row0 + ar + 64) * K + ac);
    if (!TB) bvv = *(const float4*)(Bm + (size_t)bk * N + col0 + bn);
    else     bvv = *(const float4*)(Bm + (size_t)(col0 + tn) * K + tk);

    // ---- split + float4 store stage 0
    {
        float4 h, l;
        split4(a0v, h, l);
        *(float4*)&Ah[0][ar][ac] = h;      *(float4*)&Al[0][ar][ac] = l;
        split4(a1v, h, l);
        *(float4*)&Ah[0][ar + 64][ac] = h; *(float4*)&Al[0][ar + 64][ac] = l;
        if (!TB) {
            float hb, lb;
            split1(bvv.x, hb, lb); Bh[0][bn + 0][bk] = hb; Bl[0][bn + 0][bk] = lb;
            split1(bvv.y, hb, lb); Bh[0][bn + 1][bk] = hb; Bl[0][bn + 1][bk] = lb;
            split1(bvv.z, hb, lb); Bh[0][bn + 2][bk] = hb; Bl[0][bn + 2][bk] = lb;
            split1(bvv.w, hb, lb); Bh[0][bn + 3][bk] = hb; Bl[0][bn + 3][bk] = lb;
        } else {
            float4 h2, l2;
            split4(bvv, h2, l2);
            *(float4*)&Bh[0][tn][tk] = h2;  *(float4*)&Bl[0][tn][tk] = l2;
        }
    }
    __syncthreads();

    int buf = 0;
    for (int k0 = 16; k0 < K + 16; k0 += 16) {
        if (k0 < K) {
            a0v = *(const float4*)(A + (size_t)(row0 + ar) * K + k0 + ac);
            a1v = *(const float4*)(A + (size_t)(row0 + ar + 64) * K + k0 + ac);
            if (!TB) bvv = *(const float4*)(Bm + (size_t)(k0 + bk) * N + col0 + bn);
            else     bvv = *(const float4*)(Bm + (size_t)(col0 + tn) * K + k0 + tk);
        }
        // ---- compute on buf
        const unsigned aSt = (unsigned)buf * A_TILE;
        const unsigned bSt = (unsigned)buf * B_TILE;
#pragma unroll
        for (int kc = 0; kc < 2; kc++) {
            unsigned ah[2][4], alr[2][4], bh[2][4], blr[2][4];
#pragma unroll
            for (int mt = 0; mt < 2; mt++) {
                unsigned ad = aSt + offA + (unsigned)mt * MT_OFF + (unsigned)(kc * 32);
                ldsm4(ah[mt],  baseAh + ad);
                ldsm4(alr[mt], baseAl + ad);
            }
#pragma unroll
            for (int np = 0; np < 2; np++) {
                unsigned bd = bSt + offB + (unsigned)np * MT_OFF + (unsigned)(kc * 32);
                ldsm4(bh[np],  baseBh + bd);
                ldsm4(blr[np], baseBl + bd);
            }
#pragma unroll
            for (int mt = 0; mt < 2; mt++)
#pragma unroll
                for (int np = 0; np < 2; np++)
#pragma unroll
                    for (int hf = 0; hf < 2; hf++) {
                        float* c = acc[mt][np * 2 + hf];
                        mma_tf32(c, ah[mt],  &bh[np][hf * 2]);
                        mma_tf32(c, alr[mt], &bh[np][hf * 2]);
                        mma_tf32(c, ah[mt],  &blr[np][hf * 2]);
                    }
        }
        // ---- split + store next stage
        if (k0 < K) {
            const int nb = buf ^ 1;
            float4 h, l;
            split4(a0v, h, l);
            *(float4*)&Ah[nb][ar][ac] = h;      *(float4*)&Al[nb][ar][ac] = l;
            split4(a1v, h, l);
            *(float4*)&Ah[nb][ar + 64][ac] = h; *(float4*)&Al[nb][ar + 64][ac] = l;
            if (!TB) {
                float hb, lb;
                split1(bvv.x, hb, lb); Bh[nb][bn + 0][bk] = hb; Bl[nb][bn + 0][bk] = lb;
                split1(bvv.y, hb, lb); Bh[nb][bn + 1][bk] = hb; Bl[nb][bn + 1][bk] = lb;
                split1(bvv.z, hb, lb); Bh[nb][bn + 2][bk] = hb; Bl[nb][bn + 2][bk] = lb;
                split1(bvv.w, hb, lb); Bh[nb][bn + 3][bk] = hb; Bl[nb][bn + 3][bk] = lb;
            } else {
                float4 h2, l2;
                split4(bvv, h2, l2);
                *(float4*)&Bh[nb][tn][tk] = h2;  *(float4*)&Bl[nb][tn][tk] = l2;
            }
        }
        __syncthreads();
        buf ^= 1;
    }

    if constexpr (ARGMAX) {
        __shared__ float s_v[128][2];
        __shared__ int   s_c[128][2];
#pragma unroll
        for (int mt = 0; mt < 2; mt++) {
#pragma unroll
            for (int half = 0; half < 2; half++) {
                const int rloc = wm * 32 + mt * 16 + (lane >> 2) + half * 8;
                float best = -1e30f;
                int bc = 0;
#pragma unroll
                for (int nt = 0; nt < 4; nt++) {
                    const int cl = wn * 32 + nt * 8 + (lane & 3) * 2;
                    float v0 = acc[mt][nt][half * 2];
                    float v1 = acc[mt][nt][half * 2 + 1];
                    if (v0 > best) { best = v0; bc = cl; }
                    if (v1 > best) { best = v1; bc = cl + 1; }
                }
#pragma unroll
                for (int o = 1; o < 4; o <<= 1) {
                    float ov = __shfl_xor_sync(0xffffffffu, best, o);
                    int   oc = __shfl_xor_sync(0xffffffffu, bc, o);
                    if (ov > best || (ov == best && oc < bc)) { best = ov; bc = oc; }
                }
                if ((lane & 3) == 0) { s_v[rloc][wn] = best; s_c[rloc][wn] = bc; }
            }
        }
        __syncthreads();
        if (tid < 128) {
            float best = s_v[tid][0];
            int bc = s_c[tid][0];
            if (s_v[tid][1] > best) { best = s_v[tid][1]; bc = s_c[tid][1]; }
            g_pval[(size_t)(row0 + tid) * 16 + blockIdx.x] = best;
            g_pidx[(size_t)(row0 + tid) * 16 + blockIdx.x] = col0 + bc;
        }
    } else {
#pragma unroll
        for (int mt = 0; mt < 2; mt++) {
            const int r0 = row0 + wm * 32 + mt * 16 + (lane >> 2);
#pragma unroll
            for (int nt = 0; nt < 4; nt++) {
                const int cc = col0 + wn * 32 + nt * 8 + (lane & 3) * 2;
                float b0 = 0.f, b1 = 0.f;
                if (BIAS) { b0 = bias[cc]; b1 = bias[cc + 1]; }
                float2 r0v = make_float2(acc[mt][nt][0] + b0, acc[mt][nt][1] + b1);
                float2 r1v = make_float2(acc[mt][nt][2] + b0, acc[mt][nt][3] + b1);
                *(float2*)&C[(size_t)r0 * N + cc] = r0v;
                *(float2*)&C[(size_t)(r0 + 8) * N + cc] = r1v;
                if (KVH && cc >= P_DIM) {
                    // bf16 copy of K|V planes (columns P_DIM..3*P_DIM-1)
                    __nv_bfloat162* d0 =
                        (__nv_bfloat162*)&g_kvh[(size_t)r0 * (2 * P_DIM) + cc - P_DIM];
                    __nv_bfloat162* d1 =
                        (__nv_bfloat162*)&g_kvh[(size_t)(r0 + 8) * (2 * P_DIM) + cc - P_DIM];
                    *d0 = __float22bfloat162_rn(r0v);
                    *d1 = __float22bfloat162_rn(r1v);
                }
            }
        }
    }
}

__global__ void __launch_bounds__(256)
k_gemm_proj(const float* __restrict__ X, const float* __restrict__ W,
            const float* __restrict__ b) {
    mma_gemm_body<P_DIM, IN_DIM, false, true, false, false>(X, W, b, g_zpre);
}
__global__ void __launch_bounds__(256) k_gemm_scores() {
    mma_gemm_body<NPENTA, P_DIM, true, false, true, false>(g_z, g_cent, nullptr, nullptr);
}
__global__ void __launch_bounds__(256)
k_gemm_qkv(const float* __restrict__ W, const float* __restrict__ b) {
    mma_gemm_body<3 * P_DIM, P_DIM, false, true, false, true>(g_z, W, b, g_qkv);
}

// ============================================================================
// LayerNorm + GELU + L2-normalize per row (512). 128 threads, float4/thread.
// ============================================================================
__global__ void __launch_bounds__(128)
k_lgn(const float* __restrict__ gam, const float* __restrict__ bet) {
    __shared__ float wred[4];
    int row = blockIdx.x, tid = threadIdx.x;
    int lane = tid & 31, warp = tid >> 5;
    const float4* src = (const float4*)(g_zpre + (size_t)row * P_DIM);
    float4 x = src[tid];
    float s = warp_sum(x.x + x.y + x.z + x.w);
    if (lane == 0) wred[warp] = s;
    __syncthreads();
    float mu = (wred[0] + wred[1] + wred[2] + wred[3]) * (1.0f / 512.0f);
    __syncthreads();
    float4 d = make_float4(x.x - mu, x.y - mu, x.z - mu, x.w - mu);
    s = warp_sum(d.x * d.x + d.y * d.y + d.z * d.z + d.w * d.w);
    if (lane == 0) wred[warp] = s;
    __syncthreads();
    float var = (wred[0] + wred[1] + wred[2] + wred[3]) * (1.0f / 512.0f);
    __syncthreads();
    float rs = rsqrtf(var + EPS_);
    float4 gv = ((const float4*)gam)[tid];
    float4 bv = ((const float4*)bet)[tid];
    float4 hh;
    hh.x = gelu_exact(d.x * rs * gv.x + bv.x);
    hh.y = gelu_exact(d.y * rs * gv.y + bv.y);
    hh.z = gelu_exact(d.z * rs * gv.z + bv.z);
    hh.w = gelu_exact(d.w * rs * gv.w + bv.w);
    s = warp_sum(hh.x * hh.x + hh.y * hh.y + hh.z * hh.z + hh.w * hh.w);
    if (lane == 0) wred[warp] = s;
    __syncthreads();
    float nrm = sqrtf(wred[0] + wred[1] + wred[2] + wred[3]);
    float inv = 1.0f / fmaxf(nrm, 1e-12f);
    float4* dst = (float4*)(g_z + (size_t)row * P_DIM);
    dst[tid] = make_float4(hh.x * inv, hh.y * inv, hh.z * inv, hh.w * inv);
}

// ============================================================================
// Combine 16 col-block argmax partials (ascending, strict > = first index)
// ============================================================================
__global__ void k_anchor_reduce() {
    int row = blockIdx.x * 256 + threadIdx.x;
    if (row >= ROWS) return;
    float best = g_pval[(size_t)row * 16];
    int bi = g_pidx[(size_t)row * 16];
#pragma unroll
    for (int c = 1; c < 16; c++) {
        float v = g_pval[(size_t)row * 16 + c];
        if (v > best) { best = v; bi = g_pidx[(size_t)row * 16 + c]; }
    }
    g_anchor[row] = bi;
}

// ============================================================================
// Exact 128-NN per (batch, anchor) via histogram select on key
// (dist_bits<<32)|idx — same set as jax top_k(-dist) incl. tie-breaks.
// ============================================================================
__global__ void __launch_bounds__(256) k_topk(const float* __restrict__ positions) {
    __shared__ unsigned int db[S_];
    __shared__ unsigned int hist[2048];
    __shared__ unsigned long long cand[S_];
    __shared__ int scan[256];
    __shared__ int sb[4];
    int blk = blockIdx.x;
    int b = blk >> 10;
    int a = blk & 1023;
    int tid = threadIdx.x;
    if (tid == 0) { sb[2] = 0; sb[3] = 0; }
    float pq = positions[a];
    for (int i = tid; i < 2048; i += 256) hist[i] = 0;
    __syncthreads();
    for (int i = tid; i < S_; i += 256) {
        float p = positions[g_anchor[b * S_ + i]];
        unsigned int u = __float_as_uint(fabsf(pq - p));
        db[i] = u;
        atomicAdd(&hist[u >> 21], 1u);
    }
    __syncthreads();
    int base = tid * 8;
    unsigned int c[8];
    int loc = 0;
#pragma unroll
    for (int j = 0; j < 8; j++) { c[j] = hist[base + j]; loc += (int)c[j]; }
    int v = loc;
    scan[tid] = v;
    __syncthreads();
    for (int off = 1; off < 256; off <<= 1) {
        int t = (tid >= off) ? scan[tid - off] : 0;
        __syncthreads();
        v += t;
        scan[tid] = v;
        __syncthreads();
    }
    int run = v - loc;
#pragma unroll
    for (int j = 0; j < 8; j++) {
        int cnt = (int)c[j];
        if (run < KNEI && run + cnt >= KNEI) { sb[0] = base + j; sb[1] = run; }
        run += cnt;
    }
    __syncthreads();
    unsigned int bstar = (unsigned int)sb[0];
    int c0 = sb[1];
    int out = blk * KNEI;
    for (int i = tid; i < S_; i += 256) {
        unsigned int bkt = db[i] >> 21;
        if (bkt < bstar) {
            int s2 = atomicAdd(&sb[2], 1);
            g_routes[out + s2] = i;
        } else if (bkt == bstar) {
            int cp = atomicAdd(&sb[3], 1);
            cand[cp] = ((unsigned long long)db[i] << 32) | (unsigned int)i;
        }
    }
    __syncthreads();
    int ncand = sb[3];
    int need = KNEI - c0;
    int P = 1;
    while (P < ncand) P <<= 1;
    if (P < 2) P = 2;
    for (int i = ncand + tid; i < P; i += 256) cand[i] = 0xFFFFFFFFFFFFFFFFull;
    __syncthreads();
    for (int len = 2; len <= P; len <<= 1) {
        for (int j = len >> 1; j > 0; j >>= 1) {
            for (int i = tid; i < P; i += 256) {
                int p = i ^ j;
                if (p > i) {
                    bool up = ((i & len) == 0);
                    unsigned long long x = cand[i], y = cand[p];
                    if ((x > y) == up) { cand[i] = y; cand[p] = x; }
                }
            }
            __syncthreads();
        }
    }
    for (int r = tid; r < need; r += 256) g_routes[out + c0 + r] = (int)(cand[r] & 0xffffffffu);
}

// ============================================================================
// Gathered attention: block per (b,q); warp per head, barrier-free mainloop.
// K/V read as bf16 (half traffic); q and accumulation fp32.
// ============================================================================
__global__ void __launch_bounds__(256) k_attention() {
    __shared__ int   rkv[KNEI];
    __shared__ float sc[H_][KNEI];
    int row = blockIdx.x;
    int b = row >> 11;
    int tid = threadIdx.x;
    int warp = tid >> 5, lane = tid & 31;
    int anc = g_anchor[row];
    if (tid < KNEI)
        rkv[tid] = (b * S_ + g_routes[((b << 10) + anc) * KNEI + tid]) * (2 * P_DIM);
    __syncthreads();

    const int h = warp;
    const int hoff = h * HD_;
    const size_t qrow = (size_t)row * (3 * P_DIM);
    const int qd = (lane & 7) * 8;
    const int ng = lane >> 3;

    float4 q0 = *(const float4*)&g_qkv[qrow + hoff + qd];
    float4 q1 = *(const float4*)&g_qkv[qrow + hoff + qd + 4];

#pragma unroll 4
    for (int rep = 0; rep < 32; rep++) {
        int n = rep * 4 + ng;
        // 8 bf16 K values = 16B
        uint4 kraw = *(const uint4*)&g_kvh[(size_t)rkv[n] + hoff + qd];
        const __nv_bfloat162* kp = (const __nv_bfloat162*)&kraw;
        float2 k0 = __bfloat1622float2(kp[0]);
        float2 k1 = __bfloat1622float2(kp[1]);
        float2 k2 = __bfloat1622float2(kp[2]);
        float2 k3 = __bfloat1622float2(kp[3]);
        float s = q0.x * k0.x + q0.y * k0.y + q0.z * k1.x + q0.w * k1.y
                + q1.x * k2.x + q1.y * k2.y + q1.z * k3.x + q1.w * k3.y;
        s += __shfl_xor_sync(0xffffffffu, s, 4);
        s += __shfl_xor_sync(0xffffffffu, s, 2);
        s += __shfl_xor_sync(0xffffffffu, s, 1);
        if ((lane & 7) == 0) sc[h][n] = s * 0.125f;
    }
    __syncwarp();

    float v0 = sc[h][lane], v1 = sc[h][lane + 32];
    float v2 = sc[h][lane + 64], v3 = sc[h][lane + 96];
    float m = fmaxf(fmaxf(v0, v1), fmaxf(v2, v3));
#pragma unroll
    for (int o = 16; o; o >>= 1) m = fmaxf(m, __shfl_xor_sync(0xffffffffu, m, o));
    v0 = expf(v0 - m); v1 = expf(v1 - m); v2 = expf(v2 - m); v3 = expf(v3 - m);
    float ssum = warp_sum(v0 + v1 + v2 + v3);
    float inv = 1.0f / ssum;
    sc[h][lane] = v0; sc[h][lane + 32] = v1;
    sc[h][lane + 64] = v2; sc[h][lane + 96] = v3;
    __syncwarp();

    float2 acc = make_float2(0.f, 0.f);
    const int d2 = lane * 2;
#pragma unroll 4
    for (int i = 0; i < KNEI; i++) {
        float p = sc[h][i];
        float2 vv = __bfloat1622float2(
            *(const __nv_bfloat162*)&g_kvh[(size_t)rkv[i] + P_DIM + hoff + d2]);
        acc.x += p * vv.x;
        acc.y += p * vv.y;
    }
    float* dst = &g_att[(size_t)row * P_DIM + hoff + d2];
    dst[0] = acc.x * inv;
    dst[1] = acc.y * inv;
}

// ============================================================================
// Pooling + out projection folded after the mean
// ============================================================================
__global__ void k_attmean1() {
    int bb = blockIdx.x;
    int b  = bb >> 6;
    int dc = (bb >> 4) & 3;
    int sc = bb & 15;
    int d = dc * 128 + threadIdx.x;
    float s = 0.f;
    int base = (b * S_ + sc * 128) * P_DIM + d;
    for (int t = 0; t < 128; t++) s += g_att[base + t * P_DIM];
    g_attpart[(b * 16 + sc) * P_DIM + d] = s;
}
__global__ void k_attmean2() {
    int b = blockIdx.x >> 2, dc = blockIdx.x & 3;
    int d = dc * 128 + threadIdx.x;
    float s = 0.f;
#pragma unroll
    for (int p = 0; p < 16; p++) s += g_attpart[(b * 16 + p) * P_DIM + d];
    g_attmean[b * P_DIM + d] = s * (1.0f / (float)S_);
}
__global__ void k_pool(const float* __restrict__ outW, const float* __restrict__ outb) {
    __shared__ float am[P_DIM];
    int b = blockIdx.x, n = threadIdx.x;
    am[n] = g_attmean[b * P_DIM + n];
    __syncthreads();
    float acc = outb[n];
#pragma unroll 8
    for (int k = 0; k < P_DIM; k++) acc += am[k] * outW[k * P_DIM + n];
    g_pooled[b * P_DIM + n] = acc;
}

// ============================================================================
// Per-scale MLP heads
// ============================================================================
template <int TWOS>
__global__ void k_mlp1(const float* __restrict__ w1, const float* __restrict__ b1,
                       const float* __restrict__ gam, const float* __restrict__ bet) {
    __shared__ float pr[P_DIM];
    __shared__ float red[TWOS];
    int b = blockIdx.x, j = threadIdx.x;
    for (int k = j; k < P_DIM; k += TWOS) pr[k] = g_pooled[b * P_DIM + k];
    __syncthreads();
    float t = b1[j];
#pragma unroll 8
    for (int k = 0; k < P_DIM; k++) t += pr[k] * w1[k * TWOS + j];
    float mu = block_sum(t, red, TWOS, j) / (float)TWOS;
    float d = t - mu;
    float var = block_sum(d * d, red, TWOS, j) / (float)TWOS;
    float y = d * rsqrtf(var + EPS_) * gam[j] + bet[j];
    g_h[b * 1024 + j] = gelu_exact(y);
}

template <int TWOS, int SS, int OFF>
__global__ void k_mlp2(const float* __restrict__ w2, const float* __restrict__ b2,
                       float* __restrict__ out) {
    __shared__ float hr[TWOS];
    int b = blockIdx.x, j = threadIdx.x;
    for (int k = j; k < TWOS; k += SS) hr[k] = g_h[b * 1024 + k];
    __syncthreads();
    float acc = b2[j];
#pragma unroll 8
    for (int k = 0; k < TWOS; k++) acc += hr[k] * w2[k * SS + j];
    out[b * 896 + OFF + j] = acc;
}

// ============================================================================
// Launch
// ============================================================================
extern "C" void kernel_launch(void* const* d_in, const int* in_sizes, int n_in,
                              void* d_out, int out_size) {
    const float* X      = (const float*)d_in[0];
    const float* penta  = (const float*)d_in[1];
    const float* poss   = (const float*)d_in[2];
    const float* projW  = (const float*)d_in[3];
    const float* projb  = (const float*)d_in[4];
    const float* lng    = (const float*)d_in[5];
    const float* lnb    = (const float*)d_in[6];
    const float* qkvW   = (const float*)d_in[7];
    const float* qkvb   = (const float*)d_in[8];
    const float* outW   = (const float*)d_in[9];
    const float* outb   = (const float*)d_in[10];
    const float* w1a = (const float*)d_in[11]; const float* b1a = (const float*)d_in[12];
    const float* ga  = (const float*)d_in[13]; const float* bba = (const float*)d_in[14];
    const float* w2a = (const float*)d_in[15]; const float* b2a = (const float*)d_in[16];
    const float* w1b = (const float*)d_in[17]; const float* b1b = (const float*)d_in[18];
    const float* gb  = (const float*)d_in[19]; const float* bbb = (const float*)d_in[20];
    const float* w2b = (const float*)d_in[21]; const float* b2b = (const float*)d_in[22];
    const float* w1c = (const float*)d_in[23]; const float* b1c = (const float*)d_in[24];
    const float* gc  = (const float*)d_in[25]; const float* bbc = (const float*)d_in[26];
    const float* w2c = (const float*)d_in[27]; const float* b2c = (const float*)d_in[28];
    float* out = (float*)d_out;

    k_cent<<<NPENTA, 256>>>(penta);
    k_gemm_proj<<<dim3(P_DIM / 64, ROWS / 128), 256>>>(X, projW, projb);
    k_lgn<<<ROWS, 128>>>(lng, lnb);
    k_gemm_scores<<<dim3(NPENTA / 64, ROWS / 128), 256>>>();
    k_anchor_reduce<<<ROWS / 256, 256>>>();
    k_gemm_qkv<<<dim3(3 * P_DIM / 64, ROWS / 128), 256>>>(qkvW, qkvb);
    k_topk<<<B_ * NPENTA, 256>>>(poss);
    k_attention<<<ROWS, 256>>>();
    k_attmean1<<<128, 128>>>();
    k_attmean2<<<8, 128>>>();
    k_pool<<<B_, 512>>>(outW, outb);

    k_mlp1<256><<<B_, 256>>>(w1a, b1a, ga, bba);
    k_mlp2<256, 128, 0><<<B_, 128>>>(w2a, b2a, out);
    k_mlp1<512><<<B_, 512>>>(w1b, b1b, gb, bbb);
    k_mlp2<512, 256, 128><<<B_, 256>>>(w2b, b2b, out);
    k_mlp1<1024><<<B_, 1024>>>(w1c, b1c, gc, bbc);
    k_mlp2<1024, 512, 384><<<B_, 512>>>(w2c, b2c, out);
}

// round 14
// speedup vs baseline: 1.6046x; 1.1028x over previous
#include <cuda_runtime.h>
#include <cuda_bf16.h>
#include <math.h>

// ============================================================================
// Problem constants
// ============================================================================
#define B_     2
#define S_     2048
#define IN_DIM 1024
#define P_DIM  512
#define H_     8
#define HD_    64
#define NPENTA 1024
#define KNEI   128
#define ROWS   (B_ * S_)        // 4096
#define EPS_   1e-5f

#define PAD    20               // fp32 smem row stride: 16B-aligned rows,
                                // conflict-free ldmatrix (20r mod 32 distinct spans)

// ============================================================================
// Scratch (static device globals — no runtime allocation)
// ============================================================================
__device__ float g_cent[NPENTA * P_DIM];
__device__ float g_zpre[ROWS * P_DIM];
__device__ float g_z[ROWS * P_DIM];
__device__ float g_pval[ROWS * 16];
__device__ int   g_pidx[ROWS * 16];
__device__ int   g_anchor[ROWS];
__device__ int   g_routes[B_ * NPENTA * KNEI];
__device__ float g_qkv[ROWS * 3 * P_DIM];
__device__ __nv_bfloat16 g_kvh[ROWS * 2 * P_DIM];  // bf16 K|V (halved attn traffic)
__device__ float g_att[ROWS * P_DIM];
__device__ float g_attpart[B_ * 16 * P_DIM];
__device__ float g_attmean[B_ * P_DIM];
__device__ float g_pooled[B_ * P_DIM];
__device__ float g_h[B_ * 1024];

// ============================================================================
// Helpers
// ============================================================================
__device__ __forceinline__ float gelu_exact(float x) {
    return 0.5f * x * (1.0f + erff(x * 0.70710678118654752440f));
}

__device__ __forceinline__ float block_sum(float v, float* red, int n, int tid) {
    red[tid] = v;
    __syncthreads();
    for (int s = n >> 1; s > 0; s >>= 1) {
        if (tid < s) red[tid] += red[tid + s];
        __syncthreads();
    }
    float r = red[0];
    __syncthreads();
    return r;
}

__device__ __forceinline__ float warp_sum(float v) {
#pragma unroll
    for (int o = 16; o; o >>= 1) v += __shfl_xor_sync(0xffffffffu, v, o);
    return v;
}

__device__ __forceinline__ unsigned cvt_tf32(float x) {
    unsigned r;
    asm("cvt.rna.tf32.f32 %0, %1;" : "=r"(r) : "f"(x));
    return r;
}

__device__ __forceinline__ void split1(float x, float& h, float& l) {
    h = __uint_as_float(cvt_tf32(x));
    l = __uint_as_float(cvt_tf32(x - h));
}

__device__ __forceinline__ void split4(const float4& v, float4& h, float4& l) {
    split1(v.x, h.x, l.x);
    split1(v.y, h.y, l.y);
    split1(v.z, h.z, l.z);
    split1(v.w, h.w, l.w);
}

__device__ __forceinline__ float4 hi4(const float4& v) {
    float4 h;
    h.x = __uint_as_float(cvt_tf32(v.x));
    h.y = __uint_as_float(cvt_tf32(v.y));
    h.z = __uint_as_float(cvt_tf32(v.z));
    h.w = __uint_as_float(cvt_tf32(v.w));
    return h;
}

__device__ __forceinline__ void mma_tf32(float* c, const unsigned* a, const unsigned* b) {
    asm volatile(
        "mma.sync.aligned.m16n8k8.row.col.f32.tf32.tf32.f32 "
        "{%0,%1,%2,%3}, {%4,%5,%6,%7}, {%8,%9}, {%0,%1,%2,%3};"
        : "+f"(c[0]), "+f"(c[1]), "+f"(c[2]), "+f"(c[3])
        : "r"(a[0]), "r"(a[1]), "r"(a[2]), "r"(a[3]), "r"(b[0]), "r"(b[1]));
}

__device__ __forceinline__ void ldsm4(unsigned* r, unsigned saddr) {
    asm volatile(
        "ldmatrix.sync.aligned.m8n8.x4.shared.b16 {%0,%1,%2,%3}, [%4];"
        : "=r"(r[0]), "=r"(r[1]), "=r"(r[2]), "=r"(r[3]) : "r"(saddr));
}

// ============================================================================
// centroids = normalize(mean over 5 vertices)
// ============================================================================
__global__ void k_cent(const float* __restrict__ penta) {
    __shared__ float red[256];
    int p = blockIdx.x, tid = threadIdx.x;
    float v[2];
    float ss = 0.f;
#pragma unroll
    for (int r = 0; r < 2; r++) {
        int d = tid + r * 256;
        float s = 0.f;
#pragma unroll
        for (int i = 0; i < 5; i++) s += penta[(p * 5 + i) * P_DIM + d];
        v[r] = s / 5.0f;
        ss += v[r] * v[r];
    }
    float tot = block_sum(ss, red, 256, tid);
    float den = fmaxf(sqrtf(tot), 1e-12f);
#pragma unroll
    for (int r = 0; r < 2; r++) g_cent[p * P_DIM + tid + r * 256] = v[r] / den;
}

// ============================================================================
// TF32 tensor-core GEMM (R8 skeleton). THREEX: 3xTF32 error compensation
// (hi/lo split, ~fp32) — used where exactness matters (proj -> LN -> argmax,
// scores -> argmax). !THREEX: single-pass tf32 (hi only, ~5e-4 rel) — used
// for qkv (continuous path only; measured bf16 1.78e-3 scales /8 to ~2.2e-4).
// KVH: epilogue writes bf16 copy of K|V planes to g_kvh.
// BM=128, BN=64, BK=16, 256 threads = 8 warps (4m x 2n), warp tile 32x32.
// ============================================================================
template <int N, int K, bool TB, bool BIAS, bool ARGMAX, bool THREEX, bool KVH>
__device__ __forceinline__ void mma_gemm_body(const float* __restrict__ A,
                                              const float* __restrict__ Bm,
                                              const float* __restrict__ bias,
                                              float* __restrict__ C) {
    __shared__ float Ah[2][128][PAD];
    __shared__ float Bh[2][64][PAD];
    __shared__ float Al[THREEX ? 2 : 1][THREEX ? 128 : 1][THREEX ? PAD : 1];
    __shared__ float Bl[THREEX ? 2 : 1][THREEX ? 64 : 1][THREEX ? PAD : 1];

    const int tid  = threadIdx.x;
    const int lane = tid & 31;
    const int warp = tid >> 5;
    const int wm = warp >> 1, wn = warp & 1;
    const int row0 = blockIdx.y * 128, col0 = blockIdx.x * 64;

    // global-load mappings (exact R8)
    const int ar = tid >> 2;            // A rows 0..63 (+64)
    const int ac = (tid & 3) * 4;       // A k-offset
    const int bk = tid >> 4;            // !TB: B row (k) 0..15
    const int bn = (tid & 15) * 4;      //      B col (n)
    const int tn = tid >> 2;            //  TB: B row (n) 0..63
    const int tk = (tid & 3) * 4;       //      B col (k)

    float acc[2][4][4];
#pragma unroll
    for (int mt = 0; mt < 2; mt++)
#pragma unroll
        for (int nt = 0; nt < 4; nt++)
#pragma unroll
            for (int r = 0; r < 4; r++) acc[mt][nt][r] = 0.f;

    const unsigned offA = ((unsigned)(wm * 32 + (lane & 15)) * PAD + (unsigned)((lane >> 4) * 4)) * 4u;
    const int brow = (lane & 7) + ((lane >> 4) << 3);
    const int bcol = ((lane >> 3) & 1) * 4;
    const unsigned offB = ((unsigned)(wn * 32 + brow) * PAD + (unsigned)bcol) * 4u;
    const unsigned baseAh = (unsigned)__cvta_generic_to_shared(&Ah[0][0][0]);
    const unsigned baseAl = (unsigned)__cvta_generic_to_shared(&Al[0][0][0]);
    const unsigned baseBh = (unsigned)__cvta_generic_to_shared(&Bh[0][0][0]);
    const unsigned baseBl = (unsigned)__cvta_generic_to_shared(&Bl[0][0][0]);
    const unsigned A_TILE = 128u * PAD * 4u;
    const unsigned B_TILE = 64u * PAD * 4u;
    const unsigned MT_OFF = 16u * PAD * 4u;

    float4 a0v, a1v, bvv;

    // ---- stage 0 global loads
    a0v = *(const float4*)(A + (size_t)(row0 + ar) * K + ac);
    a1v = *(const float4*)(A + (size_t)(row0 + ar + 64) * K + ac);
    if (!TB) bvv = *(const float4*)(Bm + (size_t)bk * N + col0 + bn);
    else     bvv = *(const float4*)(Bm + (size_t)(col0 + tn) * K + tk);

    // ---- convert + float4 store stage 0
    {
        if (THREEX) {
            float4 h, l;
            split4(a0v, h, l);
            *(float4*)&Ah[0][ar][ac] = h;      *(float4*)&Al[0][ar][ac] = l;
            split4(a1v, h, l);
            *(float4*)&Ah[0][ar + 64][ac] = h; *(float4*)&Al[0][ar + 64][ac] = l;
        } else {
            *(float4*)&Ah[0][ar][ac] = hi4(a0v);
            *(float4*)&Ah[0][ar + 64][ac] = hi4(a1v);
        }
        if (!TB) {
            if (THREEX) {
                float hb, lb;
                split1(bvv.x, hb, lb); Bh[0][bn + 0][bk] = hb; Bl[0][bn + 0][bk] = lb;
                split1(bvv.y, hb, lb); Bh[0][bn + 1][bk] = hb; Bl[0][bn + 1][bk] = lb;
                split1(bvv.z, hb, lb); Bh[0][bn + 2][bk] = hb; Bl[0][bn + 2][bk] = lb;
                split1(bvv.w, hb, lb); Bh[0][bn + 3][bk] = hb; Bl[0][bn + 3][bk] = lb;
            } else {
                float4 h = hi4(bvv);
                Bh[0][bn + 0][bk] = h.x; Bh[0][bn + 1][bk] = h.y;
                Bh[0][bn + 2][bk] = h.z; Bh[0][bn + 3][bk] = h.w;
            }
        } else {
            if (THREEX) {
                float4 h2, l2;
                split4(bvv, h2, l2);
                *(float4*)&Bh[0][tn][tk] = h2;  *(float4*)&Bl[0][tn][tk] = l2;
            } else {
                *(float4*)&Bh[0][tn][tk] = hi4(bvv);
            }
        }
    }
    __syncthreads();

    int buf = 0;
    for (int k0 = 16; k0 < K + 16; k0 += 16) {
        if (k0 < K) {
            a0v = *(const float4*)(A + (size_t)(row0 + ar) * K + k0 + ac);
            a1v = *(const float4*)(A + (size_t)(row0 + ar + 64) * K + k0 + ac);
            if (!TB) bvv = *(const float4*)(Bm + (size_t)(k0 + bk) * N + col0 + bn);
            else     bvv = *(const float4*)(Bm + (size_t)(col0 + tn) * K + k0 + tk);
        }
        // ---- compute on buf
        const unsigned aSt = (unsigned)buf * A_TILE;
        const unsigned bSt = (unsigned)buf * B_TILE;
#pragma unroll
        for (int kc = 0; kc < 2; kc++) {
            unsigned ah[2][4], alr[2][4], bh[2][4], blr[2][4];
#pragma unroll
            for (int mt = 0; mt < 2; mt++) {
                unsigned ad = aSt + offA + (unsigned)mt * MT_OFF + (unsigned)(kc * 32);
                ldsm4(ah[mt],  baseAh + ad);
                if (THREEX) ldsm4(alr[mt], baseAl + ad);
            }
#pragma unroll
            for (int np = 0; np < 2; np++) {
                unsigned bd = bSt + offB + (unsigned)np * MT_OFF + (unsigned)(kc * 32);
                ldsm4(bh[np],  baseBh + bd);
                if (THREEX) ldsm4(blr[np], baseBl + bd);
            }
#pragma unroll
            for (int mt = 0; mt < 2; mt++)
#pragma unroll
                for (int np = 0; np < 2; np++)
#pragma unroll
                    for (int hf = 0; hf < 2; hf++) {
                        float* c = acc[mt][np * 2 + hf];
                        mma_tf32(c, ah[mt],  &bh[np][hf * 2]);
                        if (THREEX) {
                            mma_tf32(c, alr[mt], &bh[np][hf * 2]);
                            mma_tf32(c, ah[mt],  &blr[np][hf * 2]);
                        }
                    }
        }
        // ---- convert + store next stage
        if (k0 < K) {
            const int nb = buf ^ 1;
            if (THREEX) {
                float4 h, l;
                split4(a0v, h, l);
                *(float4*)&Ah[nb][ar][ac] = h;      *(float4*)&Al[nb][ar][ac] = l;
                split4(a1v, h, l);
                *(float4*)&Ah[nb][ar + 64][ac] = h; *(float4*)&Al[nb][ar + 64][ac] = l;
            } else {
                *(float4*)&Ah[nb][ar][ac] = hi4(a0v);
                *(float4*)&Ah[nb][ar + 64][ac] = hi4(a1v);
            }
            if (!TB) {
                if (THREEX) {
                    float hb, lb;
                    split1(bvv.x, hb, lb); Bh[nb][bn + 0][bk] = hb; Bl[nb][bn + 0][bk] = lb;
                    split1(bvv.y, hb, lb); Bh[nb][bn + 1][bk] = hb; Bl[nb][bn + 1][bk] = lb;
                    split1(bvv.z, hb, lb); Bh[nb][bn + 2][bk] = hb; Bl[nb][bn + 2][bk] = lb;
                    split1(bvv.w, hb, lb); Bh[nb][bn + 3][bk] = hb; Bl[nb][bn + 3][bk] = lb;
                } else {
                    float4 h = hi4(bvv);
                    Bh[nb][bn + 0][bk] = h.x; Bh[nb][bn + 1][bk] = h.y;
                    Bh[nb][bn + 2][bk] = h.z; Bh[nb][bn + 3][bk] = h.w;
                }
            } else {
                if (THREEX) {
                    float4 h2, l2;
                    split4(bvv, h2, l2);
                    *(float4*)&Bh[nb][tn][tk] = h2;  *(float4*)&Bl[nb][tn][tk] = l2;
                } else {
                    *(float4*)&Bh[nb][tn][tk] = hi4(bvv);
                }
            }
        }
        __syncthreads();
        buf ^= 1;
    }

    if constexpr (ARGMAX) {
        __shared__ float s_v[128][2];
        __shared__ int   s_c[128][2];
#pragma unroll
        for (int mt = 0; mt < 2; mt++) {
#pragma unroll
            for (int half = 0; half < 2; half++) {
                const int rloc = wm * 32 + mt * 16 + (lane >> 2) + half * 8;
                float best = -1e30f;
                int bc = 0;
#pragma unroll
                for (int nt = 0; nt < 4; nt++) {
                    const int cl = wn * 32 + nt * 8 + (lane & 3) * 2;
                    float v0 = acc[mt][nt][half * 2];
                    float v1 = acc[mt][nt][half * 2 + 1];
                    if (v0 > best) { best = v0; bc = cl; }
                    if (v1 > best) { best = v1; bc = cl + 1; }
                }
#pragma unroll
                for (int o = 1; o < 4; o <<= 1) {
                    float ov = __shfl_xor_sync(0xffffffffu, best, o);
                    int   oc = __shfl_xor_sync(0xffffffffu, bc, o);
                    if (ov > best || (ov == best && oc < bc)) { best = ov; bc = oc; }
                }
                if ((lane & 3) == 0) { s_v[rloc][wn] = best; s_c[rloc][wn] = bc; }
            }
        }
        __syncthreads();
        if (tid < 128) {
            float best = s_v[tid][0];
            int bc = s_c[tid][0];
            if (s_v[tid][1] > best) { best = s_v[tid][1]; bc = s_c[tid][1]; }
            g_pval[(size_t)(row0 + tid) * 16 + blockIdx.x] = best;
            g_pidx[(size_t)(row0 + tid) * 16 + blockIdx.x] = col0 + bc;
        }
    } else {
#pragma unroll
        for (int mt = 0; mt < 2; mt++) {
            const int r0 = row0 + wm * 32 + mt * 16 + (lane >> 2);
#pragma unroll
            for (int nt = 0; nt < 4; nt++) {
                const int cc = col0 + wn * 32 + nt * 8 + (lane & 3) * 2;
                float b0 = 0.f, b1 = 0.f;
                if (BIAS) { b0 = bias[cc]; b1 = bias[cc + 1]; }
                float2 r0v = make_float2(acc[mt][nt][0] + b0, acc[mt][nt][1] + b1);
                float2 r1v = make_float2(acc[mt][nt][2] + b0, acc[mt][nt][3] + b1);
                *(float2*)&C[(size_t)r0 * N + cc] = r0v;
                *(float2*)&C[(size_t)(r0 + 8) * N + cc] = r1v;
                if (KVH && cc >= P_DIM) {
                    *(__nv_bfloat162*)&g_kvh[(size_t)r0 * (2 * P_DIM) + cc - P_DIM] =
                        __float22bfloat162_rn(r0v);
                    *(__nv_bfloat162*)&g_kvh[(size_t)(r0 + 8) * (2 * P_DIM) + cc - P_DIM] =
                        __float22bfloat162_rn(r1v);
                }
            }
        }
    }
}

__global__ void __launch_bounds__(256)
k_gemm_proj(const float* __restrict__ X, const float* __restrict__ W,
            const float* __restrict__ b) {
    mma_gemm_body<P_DIM, IN_DIM, false, true, false, true, false>(X, W, b, g_zpre);
}
__global__ void __launch_bounds__(256) k_gemm_scores() {
    mma_gemm_body<NPENTA, P_DIM, true, false, true, true, false>(g_z, g_cent, nullptr, nullptr);
}
__global__ void __launch_bounds__(256)
k_gemm_qkv(const float* __restrict__ W, const float* __restrict__ b) {
    mma_gemm_body<3 * P_DIM, P_DIM, false, true, false, false, true>(g_z, W, b, g_qkv);
}

// ============================================================================
// LayerNorm + GELU + L2-normalize per row (512). 128 threads, float4/thread.
// ============================================================================
__global__ void __launch_bounds__(128)
k_lgn(const float* __restrict__ gam, const float* __restrict__ bet) {
    __shared__ float wred[4];
    int row = blockIdx.x, tid = threadIdx.x;
    int lane = tid & 31, warp = tid >> 5;
    const float4* src = (const float4*)(g_zpre + (size_t)row * P_DIM);
    float4 x = src[tid];
    float s = warp_sum(x.x + x.y + x.z + x.w);
    if (lane == 0) wred[warp] = s;
    __syncthreads();
    float mu = (wred[0] + wred[1] + wred[2] + wred[3]) * (1.0f / 512.0f);
    __syncthreads();
    float4 d = make_float4(x.x - mu, x.y - mu, x.z - mu, x.w - mu);
    s = warp_sum(d.x * d.x + d.y * d.y + d.z * d.z + d.w * d.w);
    if (lane == 0) wred[warp] = s;
    __syncthreads();
    float var = (wred[0] + wred[1] + wred[2] + wred[3]) * (1.0f / 512.0f);
    __syncthreads();
    float rs = rsqrtf(var + EPS_);
    float4 gv = ((const float4*)gam)[tid];
    float4 bv = ((const float4*)bet)[tid];
    float4 hh;
    hh.x = gelu_exact(d.x * rs * gv.x + bv.x);
    hh.y = gelu_exact(d.y * rs * gv.y + bv.y);
    hh.z = gelu_exact(d.z * rs * gv.z + bv.z);
    hh.w = gelu_exact(d.w * rs * gv.w + bv.w);
    s = warp_sum(hh.x * hh.x + hh.y * hh.y + hh.z * hh.z + hh.w * hh.w);
    if (lane == 0) wred[warp] = s;
    __syncthreads();
    float nrm = sqrtf(wred[0] + wred[1] + wred[2] + wred[3]);
    float inv = 1.0f / fmaxf(nrm, 1e-12f);
    float4* dst = (float4*)(g_z + (size_t)row * P_DIM);
    dst[tid] = make_float4(hh.x * inv, hh.y * inv, hh.z * inv, hh.w * inv);
}

// ============================================================================
// Combine 16 col-block argmax partials (ascending, strict > = first index)
// ============================================================================
__global__ void k_anchor_reduce() {
    int row = blockIdx.x * 256 + threadIdx.x;
    if (row >= ROWS) return;
    float best = g_pval[(size_t)row * 16];
    int bi = g_pidx[(size_t)row * 16];
#pragma unroll
    for (int c = 1; c < 16; c++) {
        float v = g_pval[(size_t)row * 16 + c];
        if (v > best) { best = v; bi = g_pidx[(size_t)row * 16 + c]; }
    }
    g_anchor[row] = bi;
}

// ============================================================================
// Exact 128-NN per (batch, anchor) via histogram select on key
// (dist_bits<<32)|idx — same set as jax top_k(-dist) incl. tie-breaks.
// ============================================================================
__global__ void __launch_bounds__(256) k_topk(const float* __restrict__ positions) {
    __shared__ unsigned int db[S_];
    __shared__ unsigned int hist[2048];
    __shared__ unsigned long long cand[S_];
    __shared__ int scan[256];
    __shared__ int sb[4];
    int blk = blockIdx.x;
    int b = blk >> 10;
    int a = blk & 1023;
    int tid = threadIdx.x;
    if (tid == 0) { sb[2] = 0; sb[3] = 0; }
    float pq = positions[a];
    for (int i = tid; i < 2048; i += 256) hist[i] = 0;
    __syncthreads();
    for (int i = tid; i < S_; i += 256) {
        float p = positions[g_anchor[b * S_ + i]];
        unsigned int u = __float_as_uint(fabsf(pq - p));
        db[i] = u;
        atomicAdd(&hist[u >> 21], 1u);
    }
    __syncthreads();
    int base = tid * 8;
    unsigned int c[8];
    int loc = 0;
#pragma unroll
    for (int j = 0; j < 8; j++) { c[j] = hist[base + j]; loc += (int)c[j]; }
    int v = loc;
    scan[tid] = v;
    __syncthreads();
    for (int off = 1; off < 256; off <<= 1) {
        int t = (tid >= off) ? scan[tid - off] : 0;
        __syncthreads();
        v += t;
        scan[tid] = v;
        __syncthreads();
    }
    int run = v - loc;
#pragma unroll
    for (int j = 0; j < 8; j++) {
        int cnt = (int)c[j];
        if (run < KNEI && run + cnt >= KNEI) { sb[0] = base + j; sb[1] = run; }
        run += cnt;
    }
    __syncthreads();
    unsigned int bstar = (unsigned int)sb[0];
    int c0 = sb[1];
    int out = blk * KNEI;
    for (int i = tid; i < S_; i += 256) {
        unsigned int bkt = db[i] >> 21;
        if (bkt < bstar) {
            int s2 = atomicAdd(&sb[2], 1);
            g_routes[out + s2] = i;
        } else if (bkt == bstar) {
            int cp = atomicAdd(&sb[3], 1);
            cand[cp] = ((unsigned long long)db[i] << 32) | (unsigned int)i;
        }
    }
    __syncthreads();
    int ncand = sb[3];
    int need = KNEI - c0;
    int P = 1;
    while (P < ncand) P <<= 1;
    if (P < 2) P = 2;
    for (int i = ncand + tid; i < P; i += 256) cand[i] = 0xFFFFFFFFFFFFFFFFull;
    __syncthreads();
    for (int len = 2; len <= P; len <<= 1) {
        for (int j = len >> 1; j > 0; j >>= 1) {
            for (int i = tid; i < P; i += 256) {
                int p = i ^ j;
                if (p > i) {
                    bool up = ((i & len) == 0);
                    unsigned long long x = cand[i], y = cand[p];
                    if ((x > y) == up) { cand[i] = y; cand[p] = x; }
                }
            }
            __syncthreads();
        }
    }
    for (int r = tid; r < need; r += 256) g_routes[out + c0 + r] = (int)(cand[r] & 0xffffffffu);
}

// ============================================================================
// Gathered attention: block per (b,q); warp per head, barrier-free mainloop.
// K/V read as bf16 (half traffic); q and accumulation fp32.
// ============================================================================
__global__ void __launch_bounds__(256) k_attention() {
    __shared__ int   rkv[KNEI];
    __shared__ float sc[H_][KNEI];
    int row = blockIdx.x;
    int b = row >> 11;
    int tid = threadIdx.x;
    int warp = tid >> 5, lane = tid & 31;
    int anc = g_anchor[row];
    if (tid < KNEI)
        rkv[tid] = (b * S_ + g_routes[((b << 10) + anc) * KNEI + tid]) * (2 * P_DIM);
    __syncthreads();

    const int h = warp;
    const int hoff = h * HD_;
    const size_t qrow = (size_t)row * (3 * P_DIM);
    const int qd = (lane & 7) * 8;
    const int ng = lane >> 3;

    float4 q0 = *(const float4*)&g_qkv[qrow + hoff + qd];
    float4 q1 = *(const float4*)&g_qkv[qrow + hoff + qd + 4];

#pragma unroll 4
    for (int rep = 0; rep < 32; rep++) {
        int n = rep * 4 + ng;
        uint4 kraw = *(const uint4*)&g_kvh[(size_t)rkv[n] + hoff + qd];
        const __nv_bfloat162* kp = (const __nv_bfloat162*)&kraw;
        float2 k0 = __bfloat1622float2(kp[0]);
        float2 k1 = __bfloat1622float2(kp[1]);
        float2 k2 = __bfloat1622float2(kp[2]);
        float2 k3 = __bfloat1622float2(kp[3]);
        float s = q0.x * k0.x + q0.y * k0.y + q0.z * k1.x + q0.w * k1.y
                + q1.x * k2.x + q1.y * k2.y + q1.z * k3.x + q1.w * k3.y;
        s += __shfl_xor_sync(0xffffffffu, s, 4);
        s += __shfl_xor_sync(0xffffffffu, s, 2);
        s += __shfl_xor_sync(0xffffffffu, s, 1);
        if ((lane & 7) == 0) sc[h][n] = s * 0.125f;
    }
    __syncwarp();

    float v0 = sc[h][lane], v1 = sc[h][lane + 32];
    float v2 = sc[h][lane + 64], v3 = sc[h][lane + 96];
    float m = fmaxf(fmaxf(v0, v1), fmaxf(v2, v3));
#pragma unroll
    for (int o = 16; o; o >>= 1) m = fmaxf(m, __shfl_xor_sync(0xffffffffu, m, o));
    v0 = expf(v0 - m); v1 = expf(v1 - m); v2 = expf(v2 - m); v3 = expf(v3 - m);
    float ssum = warp_sum(v0 + v1 + v2 + v3);
    float inv = 1.0f / ssum;
    sc[h][lane] = v0; sc[h][lane + 32] = v1;
    sc[h][lane + 64] = v2; sc[h][lane + 96] = v3;
    __syncwarp();

    float2 acc = make_float2(0.f, 0.f);
    const int d2 = lane * 2;
#pragma unroll 4
    for (int i = 0; i < KNEI; i++) {
        float p = sc[h][i];
        float2 vv = __bfloat1622float2(
            *(const __nv_bfloat162*)&g_kvh[(size_t)rkv[i] + P_DIM + hoff + d2]);
        acc.x += p * vv.x;
        acc.y += p * vv.y;
    }
    float* dst = &g_att[(size_t)row * P_DIM + hoff + d2];
    dst[0] = acc.x * inv;
    dst[1] = acc.y * inv;
}

// ============================================================================
// Pooling + out projection folded after the mean
// ============================================================================
__global__ void k_attmean1() {
    int bb = blockIdx.x;
    int b  = bb >> 6;
    int dc = (bb >> 4) & 3;
    int sc = bb & 15;
    int d = dc * 128 + threadIdx.x;
    float s = 0.f;
    int base = (b * S_ + sc * 128) * P_DIM + d;
    for (int t = 0; t < 128; t++) s += g_att[base + t * P_DIM];
    g_attpart[(b * 16 + sc) * P_DIM + d] = s;
}
__global__ void k_attmean2() {
    int b = blockIdx.x >> 2, dc = blockIdx.x & 3;
    int d = dc * 128 + threadIdx.x;
    float s = 0.f;
#pragma unroll
    for (int p = 0; p < 16; p++) s += g_attpart[(b * 16 + p) * P_DIM + d];
    g_attmean[b * P_DIM + d] = s * (1.0f / (float)S_);
}
__global__ void k_pool(const float* __restrict__ outW, const float* __restrict__ outb) {
    __shared__ float am[P_DIM];
    int b = blockIdx.x, n = threadIdx.x;
    am[n] = g_attmean[b * P_DIM + n];
    __syncthreads();
    float acc = outb[n];
#pragma unroll 8
    for (int k = 0; k < P_DIM; k++) acc += am[k] * outW[k * P_DIM + n];
    g_pooled[b * P_DIM + n] = acc;
}

// ============================================================================
// Per-scale MLP heads
// ============================================================================
template <int TWOS>
__global__ void k_mlp1(const float* __restrict__ w1, const float* __restrict__ b1,
                       const float* __restrict__ gam, const float* __restrict__ bet) {
    __shared__ float pr[P_DIM];
    __shared__ float red[TWOS];
    int b = blockIdx.x, j = threadIdx.x;
    for (int k = j; k < P_DIM; k += TWOS) pr[k] = g_pooled[b * P_DIM + k];
    __syncthreads();
    float t = b1[j];
#pragma unroll 8
    for (int k = 0; k < P_DIM; k++) t += pr[k] * w1[k * TWOS + j];
    float mu = block_sum(t, red, TWOS, j) / (float)TWOS;
    float d = t - mu;
    float var = block_sum(d * d, red, TWOS, j) / (float)TWOS;
    float y = d * rsqrtf(var + EPS_) * gam[j] + bet[j];
    g_h[b * 1024 + j] = gelu_exact(y);
}

template <int TWOS, int SS, int OFF>
__global__ void k_mlp2(const float* __restrict__ w2, const float* __restrict__ b2,
                       float* __restrict__ out) {
    __shared__ float hr[TWOS];
    int b = blockIdx.x, j = threadIdx.x;
    for (int k = j; k < TWOS; k += SS) hr[k] = g_h[b * 1024 + k];
    __syncthreads();
    float acc = b2[j];
#pragma unroll 8
    for (int k = 0; k < TWOS; k++) acc += hr[k] * w2[k * SS + j];
    out[b * 896 + OFF + j] = acc;
}

// ============================================================================
// Launch
// ============================================================================
extern "C" void kernel_launch(void* const* d_in, const int* in_sizes, int n_in,
                              void* d_out, int out_size) {
    const float* X      = (const float*)d_in[0];
    const float* penta  = (const float*)d_in[1];
    const float* poss   = (const float*)d_in[2];
    const float* projW  = (const float*)d_in[3];
    const float* projb  = (const float*)d_in[4];
    const float* lng    = (const float*)d_in[5];
    const float* lnb    = (const float*)d_in[6];
    const float* qkvW   = (const float*)d_in[7];
    const float* qkvb   = (const float*)d_in[8];
    const float* outW   = (const float*)d_in[9];
    const float* outb   = (const float*)d_in[10];
    const float* w1a = (const float*)d_in[11]; const float* b1a = (const float*)d_in[12];
    const float* ga  = (const float*)d_in[13]; const float* bba = (const float*)d_in[14];
    const float* w2a = (const float*)d_in[15]; const float* b2a = (const float*)d_in[16];
    const float* w1b = (const float*)d_in[17]; const float* b1b = (const float*)d_in[18];
    const float* gb  = (const float*)d_in[19]; const float* bbb = (const float*)d_in[20];
    const float* w2b = (const float*)d_in[21]; const float* b2b = (const float*)d_in[22];
    const float* w1c = (const float*)d_in[23]; const float* b1c = (const float*)d_in[24];
    const float* gc  = (const float*)d_in[25]; const float* bbc = (const float*)d_in[26];
    const float* w2c = (const float*)d_in[27]; const float* b2c = (const float*)d_in[28];
    float* out = (float*)d_out;

    k_cent<<<NPENTA, 256>>>(penta);
    k_gemm_proj<<<dim3(P_DIM / 64, ROWS / 128), 256>>>(X, projW, projb);
    k_lgn<<<ROWS, 128>>>(lng, lnb);
    k_gemm_scores<<<dim3(NPENTA / 64, ROWS / 128), 256>>>();
    k_anchor_reduce<<<ROWS / 256, 256>>>();
    k_gemm_qkv<<<dim3(3 * P_DIM / 64, ROWS / 128), 256>>>(qkvW, qkvb);
    k_topk<<<B_ * NPENTA, 256>>>(poss);
    k_attention<<<ROWS, 256>>>();
    k_attmean1<<<128, 128>>>();
    k_attmean2<<<8, 128>>>();
    k_pool<<<B_, 512>>>(outW, outb);

    k_mlp1<256><<<B_, 256>>>(w1a, b1a, ga, bba);
    k_mlp2<256, 128, 0><<<B_, 128>>>(w2a, b2a, out);
    k_mlp1<512><<<B_, 512>>>(w1b, b1b, gb, bbb);
    k_mlp2<512, 256, 128><<<B_, 256>>>(w2b, b2b, out);
    k_mlp1<1024><<<B_, 1024>>>(w1c, b1c, gc, bbc);
    k_mlp2<1024, 512, 384><<<B_, 512>>>(w2c, b2c, out);
}

// round 16
// speedup vs baseline: 2.0121x; 1.2539x over previous
#include <cuda_runtime.h>
#include <cuda_bf16.h>
#include <math.h>

// ============================================================================
// Problem constants
// ============================================================================
#define B_     2
#define S_     2048
#define IN_DIM 1024
#define P_DIM  512
#define H_     8
#define HD_    64
#define NPENTA 1024
#define KNEI   128
#define ROWS   (B_ * S_)        // 4096
#define EPS_   1e-5f

#define PAD    20               // fp32 smem row stride: 16B-aligned rows,
                                // conflict-free ldmatrix (20r mod 32 distinct spans)

// ============================================================================
// Scratch (static device globals — no runtime allocation)
// ============================================================================
__device__ float g_cent[NPENTA * P_DIM];
__device__ float g_zpre[ROWS * P_DIM];
__device__ float g_z[ROWS * P_DIM];
__device__ float g_pval[ROWS * 16];
__device__ int   g_pidx[ROWS * 16];
__device__ int   g_anchor[ROWS];
__device__ int   g_routes[B_ * NPENTA * KNEI];
__device__ float g_qkv[ROWS * 3 * P_DIM];          // only q-plane (cols<512) written fp32
__device__ __nv_bfloat16 g_kvh[ROWS * 2 * P_DIM];  // bf16 K|V (halved attn traffic)
__device__ float g_att[ROWS * P_DIM];
__device__ float g_attpart[B_ * 64 * P_DIM];
__device__ float g_attmean[B_ * P_DIM];
__device__ float g_pooled[B_ * P_DIM];
__device__ float g_t[B_ * 1792];                   // MLP pre-LN scratch (256+512+1024)
__device__ float g_hh[B_ * 1792];                  // MLP post-GELU scratch

// ============================================================================
// Helpers
// ============================================================================
__device__ __forceinline__ float gelu_exact(float x) {
    return 0.5f * x * (1.0f + erff(x * 0.70710678118654752440f));
}

__device__ __forceinline__ float block_sum(float v, float* red, int n, int tid) {
    red[tid] = v;
    __syncthreads();
    for (int s = n >> 1; s > 0; s >>= 1) {
        if (tid < s) red[tid] += red[tid + s];
        __syncthreads();
    }
    float r = red[0];
    __syncthreads();
    return r;
}

__device__ __forceinline__ float warp_sum(float v) {
#pragma unroll
    for (int o = 16; o; o >>= 1) v += __shfl_xor_sync(0xffffffffu, v, o);
    return v;
}

__device__ __forceinline__ unsigned cvt_tf32(float x) {
    unsigned r;
    asm("cvt.rna.tf32.f32 %0, %1;" : "=r"(r) : "f"(x));
    return r;
}

__device__ __forceinline__ void split1(float x, float& h, float& l) {
    h = __uint_as_float(cvt_tf32(x));
    l = __uint_as_float(cvt_tf32(x - h));
}

__device__ __forceinline__ void split4(const float4& v, float4& h, float4& l) {
    split1(v.x, h.x, l.x);
    split1(v.y, h.y, l.y);
    split1(v.z, h.z, l.z);
    split1(v.w, h.w, l.w);
}

__device__ __forceinline__ float4 hi4(const float4& v) {
    float4 h;
    h.x = __uint_as_float(cvt_tf32(v.x));
    h.y = __uint_as_float(cvt_tf32(v.y));
    h.z = __uint_as_float(cvt_tf32(v.z));
    h.w = __uint_as_float(cvt_tf32(v.w));
    return h;
}

__device__ __forceinline__ void mma_tf32(float* c, const unsigned* a, const unsigned* b) {
    asm volatile(
        "mma.sync.aligned.m16n8k8.row.col.f32.tf32.tf32.f32 "
        "{%0,%1,%2,%3}, {%4,%5,%6,%7}, {%8,%9}, {%0,%1,%2,%3};"
        : "+f"(c[0]), "+f"(c[1]), "+f"(c[2]), "+f"(c[3])
        : "r"(a[0]), "r"(a[1]), "r"(a[2]), "r"(a[3]), "r"(b[0]), "r"(b[1]));
}

__device__ __forceinline__ void ldsm4(unsigned* r, unsigned saddr) {
    asm volatile(
        "ldmatrix.sync.aligned.m8n8.x4.shared.b16 {%0,%1,%2,%3}, [%4];"
        : "=r"(r[0]), "=r"(r[1]), "=r"(r[2]), "=r"(r[3]) : "r"(saddr));
}

// ============================================================================
// centroids = normalize(mean over 5 vertices)
// ============================================================================
__global__ void k_cent(const float* __restrict__ penta) {
    __shared__ float red[256];
    int p = blockIdx.x, tid = threadIdx.x;
    float v[2];
    float ss = 0.f;
#pragma unroll
    for (int r = 0; r < 2; r++) {
        int d = tid + r * 256;
        float s = 0.f;
#pragma unroll
        for (int i = 0; i < 5; i++) s += penta[(p * 5 + i) * P_DIM + d];
        v[r] = s / 5.0f;
        ss += v[r] * v[r];
    }
    float tot = block_sum(ss, red, 256, tid);
    float den = fmaxf(sqrtf(tot), 1e-12f);
#pragma unroll
    for (int r = 0; r < 2; r++) g_cent[p * P_DIM + tid + r * 256] = v[r] / den;
}

// ============================================================================
// TF32 tensor-core GEMM (R8 skeleton). THREEX: 3xTF32 (~fp32) for the
// argmax-critical GEMMs; !THREEX: single-pass tf32 for qkv (continuous path).
// KVH: epilogue writes fp32 q-plane only + bf16 K|V planes to g_kvh.
// BM=128, BN=64, BK=16, 256 threads = 8 warps (4m x 2n), warp tile 32x32.
// ============================================================================
template <int N, int K, bool TB, bool BIAS, bool ARGMAX, bool THREEX, bool KVH>
__device__ __forceinline__ void mma_gemm_body(const float* __restrict__ A,
                                              const float* __restrict__ Bm,
                                              const float* __restrict__ bias,
                                              float* __restrict__ C) {
    __shared__ float Ah[2][128][PAD];
    __shared__ float Bh[2][64][PAD];
    __shared__ float Al[THREEX ? 2 : 1][THREEX ? 128 : 1][THREEX ? PAD : 1];
    __shared__ float Bl[THREEX ? 2 : 1][THREEX ? 64 : 1][THREEX ? PAD : 1];

    const int tid  = threadIdx.x;
    const int lane = tid & 31;
    const int warp = tid >> 5;
    const int wm = warp >> 1, wn = warp & 1;
    const int row0 = blockIdx.y * 128, col0 = blockIdx.x * 64;

    const int ar = tid >> 2;
    const int ac = (tid & 3) * 4;
    const int bk = tid >> 4;
    const int bn = (tid & 15) * 4;
    const int tn = tid >> 2;
    const int tk = (tid & 3) * 4;

    float acc[2][4][4];
#pragma unroll
    for (int mt = 0; mt < 2; mt++)
#pragma unroll
        for (int nt = 0; nt < 4; nt++)
#pragma unroll
            for (int r = 0; r < 4; r++) acc[mt][nt][r] = 0.f;

    const unsigned offA = ((unsigned)(wm * 32 + (lane & 15)) * PAD + (unsigned)((lane >> 4) * 4)) * 4u;
    const int brow = (lane & 7) + ((lane >> 4) << 3);
    const int bcol = ((lane >> 3) & 1) * 4;
    const unsigned offB = ((unsigned)(wn * 32 + brow) * PAD + (unsigned)bcol) * 4u;
    const unsigned baseAh = (unsigned)__cvta_generic_to_shared(&Ah[0][0][0]);
    const unsigned baseAl = (unsigned)__cvta_generic_to_shared(&Al[0][0][0]);
    const unsigned baseBh = (unsigned)__cvta_generic_to_shared(&Bh[0][0][0]);
    const unsigned baseBl = (unsigned)__cvta_generic_to_shared(&Bl[0][0][0]);
    const unsigned A_TILE = 128u * PAD * 4u;
    const unsigned B_TILE = 64u * PAD * 4u;
    const unsigned MT_OFF = 16u * PAD * 4u;

    float4 a0v, a1v, bvv;

    a0v = *(const float4*)(A + (size_t)(row0 + ar) * K + ac);
    a1v = *(const float4*)(A + (size_t)(row0 + ar + 64) * K + ac);
    if (!TB) bvv = *(const float4*)(Bm + (size_t)bk * N + col0 + bn);
    else     bvv = *(const float4*)(Bm + (size_t)(col0 + tn) * K + tk);

    {
        if (THREEX) {
            float4 h, l;
            split4(a0v, h, l);
            *(float4*)&Ah[0][ar][ac] = h;      *(float4*)&Al[0][ar][ac] = l;
            split4(a1v, h, l);
            *(float4*)&Ah[0][ar + 64][ac] = h; *(float4*)&Al[0][ar + 64][ac] = l;
        } else {
            *(float4*)&Ah[0][ar][ac] = hi4(a0v);
            *(float4*)&Ah[0][ar + 64][ac] = hi4(a1v);
        }
        if (!TB) {
            if (THREEX) {
                float hb, lb;
                split1(bvv.x, hb, lb); Bh[0][bn + 0][bk] = hb; Bl[0][bn + 0][bk] = lb;
                split1(bvv.y, hb, lb); Bh[0][bn + 1][bk] = hb; Bl[0][bn + 1][bk] = lb;
                split1(bvv.z, hb, lb); Bh[0][bn + 2][bk] = hb; Bl[0][bn + 2][bk] = lb;
                split1(bvv.w, hb, lb); Bh[0][bn + 3][bk] = hb; Bl[0][bn + 3][bk] = lb;
            } else {
                float4 h = hi4(bvv);
                Bh[0][bn + 0][bk] = h.x; Bh[0][bn + 1][bk] = h.y;
                Bh[0][bn + 2][bk] = h.z; Bh[0][bn + 3][bk] = h.w;
            }
        } else {
            if (THREEX) {
                float4 h2, l2;
                split4(bvv, h2, l2);
                *(float4*)&Bh[0][tn][tk] = h2;  *(float4*)&Bl[0][tn][tk] = l2;
            } else {
                *(float4*)&Bh[0][tn][tk] = hi4(bvv);
            }
        }
    }
    __syncthreads();

    int buf = 0;
    for (int k0 = 16; k0 < K + 16; k0 += 16) {
        if (k0 < K) {
            a0v = *(const float4*)(A + (size_t)(row0 + ar) * K + k0 + ac);
            a1v = *(const float4*)(A + (size_t)(row0 + ar + 64) * K + k0 + ac);
            if (!TB) bvv = *(const float4*)(Bm + (size_t)(k0 + bk) * N + col0 + bn);
            else     bvv = *(const float4*)(Bm + (size_t)(col0 + tn) * K + k0 + tk);
        }
        const unsigned aSt = (unsigned)buf * A_TILE;
        const unsigned bSt = (unsigned)buf * B_TILE;
#pragma unroll
        for (int kc = 0; kc < 2; kc++) {
            unsigned ah[2][4], alr[2][4], bh[2][4], blr[2][4];
#pragma unroll
            for (int mt = 0; mt < 2; mt++) {
                unsigned ad = aSt + offA + (unsigned)mt * MT_OFF + (unsigned)(kc * 32);
                ldsm4(ah[mt],  baseAh + ad);
                if (THREEX) ldsm4(alr[mt], baseAl + ad);
            }
#pragma unroll
            for (int np = 0; np < 2; np++) {
                unsigned bd = bSt + offB + (unsigned)np * MT_OFF + (unsigned)(kc * 32);
                ldsm4(bh[np],  baseBh + bd);
                if (THREEX) ldsm4(blr[np], baseBl + bd);
            }
#pragma unroll
            for (int mt = 0; mt < 2; mt++)
#pragma unroll
                for (int np = 0; np < 2; np++)
#pragma unroll
                    for (int hf = 0; hf < 2; hf++) {
                        float* c = acc[mt][np * 2 + hf];
                        mma_tf32(c, ah[mt],  &bh[np][hf * 2]);
                        if (THREEX) {
                            mma_tf32(c, alr[mt], &bh[np][hf * 2]);
                            mma_tf32(c, ah[mt],  &blr[np][hf * 2]);
                        }
                    }
        }
        if (k0 < K) {
            const int nb = buf ^ 1;
            if (THREEX) {
                float4 h, l;
                split4(a0v, h, l);
                *(float4*)&Ah[nb][ar][ac] = h;      *(float4*)&Al[nb][ar][ac] = l;
                split4(a1v, h, l);
                *(float4*)&Ah[nb][ar + 64][ac] = h; *(float4*)&Al[nb][ar + 64][ac] = l;
            } else {
                *(float4*)&Ah[nb][ar][ac] = hi4(a0v);
                *(float4*)&Ah[nb][ar + 64][ac] = hi4(a1v);
            }
            if (!TB) {
                if (THREEX) {
                    float hb, lb;
                    split1(bvv.x, hb, lb); Bh[nb][bn + 0][bk] = hb; Bl[nb][bn + 0][bk] = lb;
                    split1(bvv.y, hb, lb); Bh[nb][bn + 1][bk] = hb; Bl[nb][bn + 1][bk] = lb;
                    split1(bvv.z, hb, lb); Bh[nb][bn + 2][bk] = hb; Bl[nb][bn + 2][bk] = lb;
                    split1(bvv.w, hb, lb); Bh[nb][bn + 3][bk] = hb; Bl[nb][bn + 3][bk] = lb;
                } else {
                    float4 h = hi4(bvv);
                    Bh[nb][bn + 0][bk] = h.x; Bh[nb][bn + 1][bk] = h.y;
                    Bh[nb][bn + 2][bk] = h.z; Bh[nb][bn + 3][bk] = h.w;
                }
            } else {
                if (THREEX) {
                    float4 h2, l2;
                    split4(bvv, h2, l2);
                    *(float4*)&Bh[nb][tn][tk] = h2;  *(float4*)&Bl[nb][tn][tk] = l2;
                } else {
                    *(float4*)&Bh[nb][tn][tk] = hi4(bvv);
                }
            }
        }
        __syncthreads();
        buf ^= 1;
    }

    if constexpr (ARGMAX) {
        __shared__ float s_v[128][2];
        __shared__ int   s_c[128][2];
#pragma unroll
        for (int mt = 0; mt < 2; mt++) {
#pragma unroll
            for (int half = 0; half < 2; half++) {
                const int rloc = wm * 32 + mt * 16 + (lane >> 2) + half * 8;
                float best = -1e30f;
                int bc = 0;
#pragma unroll
                for (int nt = 0; nt < 4; nt++) {
                    const int cl = wn * 32 + nt * 8 + (lane & 3) * 2;
                    float v0 = acc[mt][nt][half * 2];
                    float v1 = acc[mt][nt][half * 2 + 1];
                    if (v0 > best) { best = v0; bc = cl; }
                    if (v1 > best) { best = v1; bc = cl + 1; }
                }
#pragma unroll
                for (int o = 1; o < 4; o <<= 1) {
                    float ov = __shfl_xor_sync(0xffffffffu, best, o);
                    int   oc = __shfl_xor_sync(0xffffffffu, bc, o);
                    if (ov > best || (ov == best && oc < bc)) { best = ov; bc = oc; }
                }
                if ((lane & 3) == 0) { s_v[rloc][wn] = best; s_c[rloc][wn] = bc; }
            }
        }
        __syncthreads();
        if (tid < 128) {
            float best = s_v[tid][0];
            int bc = s_c[tid][0];
            if (s_v[tid][1] > best) { best = s_v[tid][1]; bc = s_c[tid][1]; }
            g_pval[(size_t)(row0 + tid) * 16 + blockIdx.x] = best;
            g_pidx[(size_t)(row0 + tid) * 16 + blockIdx.x] = col0 + bc;
        }
    } else {
#pragma unroll
        for (int mt = 0; mt < 2; mt++) {
            const int r0 = row0 + wm * 32 + mt * 16 + (lane >> 2);
#pragma unroll
            for (int nt = 0; nt < 4; nt++) {
                const int cc = col0 + wn * 32 + nt * 8 + (lane & 3) * 2;
                float b0 = 0.f, b1 = 0.f;
                if (BIAS) { b0 = bias[cc]; b1 = bias[cc + 1]; }
                float2 r0v = make_float2(acc[mt][nt][0] + b0, acc[mt][nt][1] + b1);
                float2 r1v = make_float2(acc[mt][nt][2] + b0, acc[mt][nt][3] + b1);
                if (!KVH || cc < P_DIM) {
                    *(float2*)&C[(size_t)r0 * N + cc] = r0v;
                    *(float2*)&C[(size_t)(r0 + 8) * N + cc] = r1v;
                }
                if (KVH && cc >= P_DIM) {
                    *(__nv_bfloat162*)&g_kvh[(size_t)r0 * (2 * P_DIM) + cc - P_DIM] =
                        __float22bfloat162_rn(r0v);
                    *(__nv_bfloat162*)&g_kvh[(size_t)(r0 + 8) * (2 * P_DIM) + cc - P_DIM] =
                        __float22bfloat162_rn(r1v);
                }
            }
        }
    }
}

__global__ void __launch_bounds__(256)
k_gemm_proj(const float* __restrict__ X, const float* __restrict__ W,
            const float* __restrict__ b) {
    mma_gemm_body<P_DIM, IN_DIM, false, true, false, true, false>(X, W, b, g_zpre);
}
__global__ void __launch_bounds__(256) k_gemm_scores() {
    mma_gemm_body<NPENTA, P_DIM, true, false, true, true, false>(g_z, g_cent, nullptr, nullptr);
}
__global__ void __launch_bounds__(256)
k_gemm_qkv(const float* __restrict__ W, const float* __restrict__ b) {
    mma_gemm_body<3 * P_DIM, P_DIM, false, true, false, false, true>(g_z, W, b, g_qkv);
}

// ============================================================================
// LayerNorm + GELU + L2-normalize per row (512). 128 threads, float4/thread.
// ============================================================================
__global__ void __launch_bounds__(128)
k_lgn(const float* __restrict__ gam, const float* __restrict__ bet) {
    __shared__ float wred[4];
    int row = blockIdx.x, tid = threadIdx.x;
    int lane = tid & 31, warp = tid >> 5;
    const float4* src = (const float4*)(g_zpre + (size_t)row * P_DIM);
    float4 x = src[tid];
    float s = warp_sum(x.x + x.y + x.z + x.w);
    if (lane == 0) wred[warp] = s;
    __syncthreads();
    float mu = (wred[0] + wred[1] + wred[2] + wred[3]) * (1.0f / 512.0f);
    __syncthreads();
    float4 d = make_float4(x.x - mu, x.y - mu, x.z - mu, x.w - mu);
    s = warp_sum(d.x * d.x + d.y * d.y + d.z * d.z + d.w * d.w);
    if (lane == 0) wred[warp] = s;
    __syncthreads();
    float var = (wred[0] + wred[1] + wred[2] + wred[3]) * (1.0f / 512.0f);
    __syncthreads();
    float rs = rsqrtf(var + EPS_);
    float4 gv = ((const float4*)gam)[tid];
    float4 bv = ((const float4*)bet)[tid];
    float4 hh;
    hh.x = gelu_exact(d.x * rs * gv.x + bv.x);
    hh.y = gelu_exact(d.y * rs * gv.y + bv.y);
    hh.z = gelu_exact(d.z * rs * gv.z + bv.z);
    hh.w = gelu_exact(d.w * rs * gv.w + bv.w);
    s = warp_sum(hh.x * hh.x + hh.y * hh.y + hh.z * hh.z + hh.w * hh.w);
    if (lane == 0) wred[warp] = s;
    __syncthreads();
    float nrm = sqrtf(wred[0] + wred[1] + wred[2] + wred[3]);
    float inv = 1.0f / fmaxf(nrm, 1e-12f);
    float4* dst = (float4*)(g_z + (size_t)row * P_DIM);
    dst[tid] = make_float4(hh.x * inv, hh.y * inv, hh.z * inv, hh.w * inv);
}

// ============================================================================
// Combine 16 col-block argmax partials (ascending, strict > = first index)
// ============================================================================
__global__ void k_anchor_reduce() {
    int row = blockIdx.x * 256 + threadIdx.x;
    if (row >= ROWS) return;
    float best = g_pval[(size_t)row * 16];
    int bi = g_pidx[(size_t)row * 16];
#pragma unroll
    for (int c = 1; c < 16; c++) {
        float v = g_pval[(size_t)row * 16 + c];
        if (v > best) { best = v; bi = g_pidx[(size_t)row * 16 + c]; }
    }
    g_anchor[row] = bi;
}

// ============================================================================
// Exact 128-NN per (batch, anchor) via histogram select on key
// (dist_bits<<32)|idx — same set as jax top_k(-dist) incl. tie-breaks.
// ============================================================================
__global__ void __launch_bounds__(256) k_topk(const float* __restrict__ positions) {
    __shared__ unsigned int db[S_];
    __shared__ unsigned int hist[2048];
    __shared__ unsigned long long cand[S_];
    __shared__ int scan[256];
    __shared__ int sb[4];
    int blk = blockIdx.x;
    int b = blk >> 10;
    int a = blk & 1023;
    int tid = threadIdx.x;
    if (tid == 0) { sb[2] = 0; sb[3] = 0; }
    float pq = positions[a];
    for (int i = tid; i < 2048; i += 256) hist[i] = 0;
    __syncthreads();
    for (int i = tid; i < S_; i += 256) {
        float p = positions[g_anchor[b * S_ + i]];
        unsigned int u = __float_as_uint(fabsf(pq - p));
        db[i] = u;
        atomicAdd(&hist[u >> 21], 1u);
    }
    __syncthreads();
    int base = tid * 8;
    unsigned int c[8];
    int loc = 0;
#pragma unroll
    for (int j = 0; j < 8; j++) { c[j] = hist[base + j]; loc += (int)c[j]; }
    int v = loc;
    scan[tid] = v;
    __syncthreads();
    for (int off = 1; off < 256; off <<= 1) {
        int t = (tid >= off) ? scan[tid - off] : 0;
        __syncthreads();
        v += t;
        scan[tid] = v;
        __syncthreads();
    }
    int run = v - loc;
#pragma unroll
    for (int j = 0; j < 8; j++) {
        int cnt = (int)c[j];
        if (run < KNEI && run + cnt >= KNEI) { sb[0] = base + j; sb[1] = run; }
        run += cnt;
    }
    __syncthreads();
    unsigned int bstar = (unsigned int)sb[0];
    int c0 = sb[1];
    int out = blk * KNEI;
    for (int i = tid; i < S_; i += 256) {
        unsigned int bkt = db[i] >> 21;
        if (bkt < bstar) {
            int s2 = atomicAdd(&sb[2], 1);
            g_routes[out + s2] = i;
        } else if (bkt == bstar) {
            int cp = atomicAdd(&sb[3], 1);
            cand[cp] = ((unsigned long long)db[i] << 32) | (unsigned int)i;
        }
    }
    __syncthreads();
    int ncand = sb[3];
    int need = KNEI - c0;
    int P = 1;
    while (P < ncand) P <<= 1;
    if (P < 2) P = 2;
    for (int i = ncand + tid; i < P; i += 256) cand[i] = 0xFFFFFFFFFFFFFFFFull;
    __syncthreads();
    for (int len = 2; len <= P; len <<= 1) {
        for (int j = len >> 1; j > 0; j >>= 1) {
            for (int i = tid; i < P; i += 256) {
                int p = i ^ j;
                if (p > i) {
                    bool up = ((i & len) == 0);
                    unsigned long long x = cand[i], y = cand[p];
                    if ((x > y) == up) { cand[i] = y; cand[p] = x; }
                }
            }
            __syncthreads();
        }
    }
    for (int r = tid; r < need; r += 256) g_routes[out + c0 + r] = (int)(cand[r] & 0xffffffffu);
}

// ============================================================================
// Gathered attention: block per (b,q); warp per head, barrier-free mainloop.
// K/V read as bf16 (half traffic); q and accumulation fp32.
// ============================================================================
__global__ void __launch_bounds__(256) k_attention() {
    __shared__ int   rkv[KNEI];
    __shared__ float sc[H_][KNEI];
    int row = blockIdx.x;
    int b = row >> 11;
    int tid = threadIdx.x;
    int warp = tid >> 5, lane = tid & 31;
    int anc = g_anchor[row];
    if (tid < KNEI)
        rkv[tid] = (b * S_ + g_routes[((b << 10) + anc) * KNEI + tid]) * (2 * P_DIM);
    __syncthreads();

    const int h = warp;
    const int hoff = h * HD_;
    const size_t qrow = (size_t)row * (3 * P_DIM);
    const int qd = (lane & 7) * 8;
    const int ng = lane >> 3;

    float4 q0 = *(const float4*)&g_qkv[qrow + hoff + qd];
    float4 q1 = *(const float4*)&g_qkv[qrow + hoff + qd + 4];

#pragma unroll 4
    for (int rep = 0; rep < 32; rep++) {
        int n = rep * 4 + ng;
        uint4 kraw = *(const uint4*)&g_kvh[(size_t)rkv[n] + hoff + qd];
        const __nv_bfloat162* kp = (const __nv_bfloat162*)&kraw;
        float2 k0 = __bfloat1622float2(kp[0]);
        float2 k1 = __bfloat1622float2(kp[1]);
        float2 k2 = __bfloat1622float2(kp[2]);
        float2 k3 = __bfloat1622float2(kp[3]);
        float s = q0.x * k0.x + q0.y * k0.y + q0.z * k1.x + q0.w * k1.y
                + q1.x * k2.x + q1.y * k2.y + q1.z * k3.x + q1.w * k3.y;
        s += __shfl_xor_sync(0xffffffffu, s, 4);
        s += __shfl_xor_sync(0xffffffffu, s, 2);
        s += __shfl_xor_sync(0xffffffffu, s, 1);
        if ((lane & 7) == 0) sc[h][n] = s * 0.125f;
    }
    __syncwarp();

    float v0 = sc[h][lane], v1 = sc[h][lane + 32];
    float v2 = sc[h][lane + 64], v3 = sc[h][lane + 96];
    float m = fmaxf(fmaxf(v0, v1), fmaxf(v2, v3));
#pragma unroll
    for (int o = 16; o; o >>= 1) m = fmaxf(m, __shfl_xor_sync(0xffffffffu, m, o));
    v0 = expf(v0 - m); v1 = expf(v1 - m); v2 = expf(v2 - m); v3 = expf(v3 - m);
    float ssum = warp_sum(v0 + v1 + v2 + v3);
    float inv = 1.0f / ssum;
    sc[h][lane] = v0; sc[h][lane + 32] = v1;
    sc[h][lane + 64] = v2; sc[h][lane + 96] = v3;
    __syncwarp();

    float2 acc = make_float2(0.f, 0.f);
    const int d2 = lane * 2;
#pragma unroll 4
    for (int i = 0; i < KNEI; i++) {
        float p = sc[h][i];
        float2 vv = __bfloat1622float2(
            *(const __nv_bfloat162*)&g_kvh[(size_t)rkv[i] + P_DIM + hoff + d2]);
        acc.x += p * vv.x;
        acc.y += p * vv.y;
    }
    float* dst = &g_att[(size_t)row * P_DIM + hoff + d2];
    dst[0] = acc.x * inv;
    dst[1] = acc.y * inv;
}

// ============================================================================
// Pooling (wide-parallel) + out projection folded after the mean
// ============================================================================
__global__ void k_attmean1() {
    int bb = blockIdx.x;             // 512 blocks: b(1) x dc(2) x sc(6 bits)
    int b  = bb >> 8;
    int dc = (bb >> 6) & 3;
    int sc = bb & 63;
    int d = dc * 128 + threadIdx.x;  // 128 threads
    float s = 0.f;
    int base = (b * S_ + sc * 32) * P_DIM + d;
    for (int t = 0; t < 32; t++) s += g_att[base + t * P_DIM];
    g_attpart[(b * 64 + sc) * P_DIM + d] = s;
}
__global__ void k_attmean2() {
    int b = blockIdx.x >> 2, dc = blockIdx.x & 3;   // 8 blocks, 128 threads
    int d = dc * 128 + threadIdx.x;
    float s = 0.f;
    for (int p = 0; p < 64; p++) s += g_attpart[(b * 64 + p) * P_DIM + d];
    g_attmean[b * P_DIM + d] = s * (1.0f / (float)S_);
}
__global__ void __launch_bounds__(128)
k_pool(const float* __restrict__ outW, const float* __restrict__ outb) {
    __shared__ float am[P_DIM];
    int b = blockIdx.x >> 2, ns = blockIdx.x & 3;   // 8 blocks
    int tid = threadIdx.x;
    for (int k = tid; k < P_DIM; k += 128) am[k] = g_attmean[b * P_DIM + k];
    __syncthreads();
    int n = ns * 128 + tid;
    float acc = outb[n];
#pragma unroll 8
    for (int k = 0; k < P_DIM; k++) acc += am[k] * outW[k * P_DIM + n];
    g_pooled[b * P_DIM + n] = acc;
}

// ============================================================================
// MLP heads, restructured for chip-wide parallelism:
//  mlpA: all three w1-GEMVs, 28 blocks x 128 (disjoint column slices)
//  mlpB: all three LayerNorm+GELU, 6 blocks x 256
//  mlpC: all three w2-GEMVs, 14 blocks x 128 -> final output
// Scratch layout per batch: scale0 @0 (256), scale1 @256 (512), scale2 @768 (1024)
// ============================================================================
__global__ void __launch_bounds__(128)
k_mlpA(const float* __restrict__ w1a, const float* __restrict__ b1a,
       const float* __restrict__ w1b, const float* __restrict__ b1b,
       const float* __restrict__ w1c, const float* __restrict__ b1c) {
    __shared__ float pr[P_DIM];
    int blk = blockIdx.x;
    int b = blk / 14, c = blk % 14;
    const float* w1; const float* b1; int twos, j0, toff;
    if (c < 2)      { w1 = w1a; b1 = b1a; twos = 256;  j0 = c * 128;        toff = 0; }
    else if (c < 6) { w1 = w1b; b1 = b1b; twos = 512;  j0 = (c - 2) * 128;  toff = 256; }
    else            { w1 = w1c; b1 = b1c; twos = 1024; j0 = (c - 6) * 128;  toff = 768; }
    int tid = threadIdx.x;
    for (int k = tid; k < P_DIM; k += 128) pr[k] = g_pooled[b * P_DIM + k];
    __syncthreads();
    int j = j0 + tid;
    float t = b1[j];
#pragma unroll 8
    for (int k = 0; k < P_DIM; k++) t += pr[k] * w1[(size_t)k * twos + j];
    g_t[b * 1792 + toff + j] = t;
}

__global__ void __launch_bounds__(256)
k_mlpB(const float* __restrict__ ga, const float* __restrict__ bba,
       const float* __restrict__ gb, const float* __restrict__ bbb,
       const float* __restrict__ gc, const float* __restrict__ bbc) {
    __shared__ float red[256];
    int blk = blockIdx.x;          // 6 = scale*2 + b
    int b = blk & 1, sc = blk >> 1;
    const float* g; const float* bb; int twos, toff;
    if (sc == 0)      { g = ga; bb = bba; twos = 256;  toff = 0; }
    else if (sc == 1) { g = gb; bb = bbb; twos = 512;  toff = 256; }
    else              { g = gc; bb = bbc; twos = 1024; toff = 768; }
    int tid = threadIdx.x;
    const float* t = &g_t[b * 1792 + toff];
    float s = 0.f;
    for (int j = tid; j < twos; j += 256) s += t[j];
    float mu = block_sum(s, red, 256, tid) / (float)twos;
    float vs = 0.f;
    for (int j = tid; j < twos; j += 256) { float d = t[j] - mu; vs += d * d; }
    float var = block_sum(vs, red, 256, tid) / (float)twos;
    float rs = rsqrtf(var + EPS_);
    for (int j = tid; j < twos; j += 256) {
        float y = (t[j] - mu) * rs * g[j] + bb[j];
        g_hh[b * 1792 + toff + j] = gelu_exact(y);
    }
}

__global__ void __launch_bounds__(128)
k_mlpC(const float* __restrict__ w2a, const float* __restrict__ b2a,
       const float* __restrict__ w2b, const float* __restrict__ b2b,
       const float* __restrict__ w2c, const float* __restrict__ b2c,
       float* __restrict__ out) {
    __shared__ float hr[1024];
    int blk = blockIdx.x;
    int b = blk / 7, c = blk % 7;
    const float* w2; const float* b2; int twos, ss, j0, toff, ooff;
    if (c < 1)      { w2 = w2a; b2 = b2a; twos = 256;  ss = 128; j0 = 0;              toff = 0;   ooff = 0; }
    else if (c < 3) { w2 = w2b; b2 = b2b; twos = 512;  ss = 256; j0 = (c - 1) * 128;  toff = 256; ooff = 128; }
    else            { w2 = w2c; b2 = b2c; twos = 1024; ss = 512; j0 = (c - 3) * 128;  toff = 768; ooff = 384; }
    int tid = threadIdx.x;
    for (int k = tid; k < twos; k += 128) hr[k] = g_hh[b * 1792 + toff + k];
    __syncthreads();
    int j = j0 + tid;
    float acc = b2[j];
#pragma unroll 8
    for (int k = 0; k < twos; k++) acc += hr[k] * w2[(size_t)k * ss + j];
    out[b * 896 + ooff + j] = acc;
}

// ============================================================================
// Launch
// ============================================================================
extern "C" void kernel_launch(void* const* d_in, const int* in_sizes, int n_in,
                              void* d_out, int out_size) {
    const float* X      = (const float*)d_in[0];
    const float* penta  = (const float*)d_in[1];
    const float* poss   = (const float*)d_in[2];
    const float* projW  = (const float*)d_in[3];
    const float* projb  = (const float*)d_in[4];
    const float* lng    = (const float*)d_in[5];
    const float* lnb    = (const float*)d_in[6];
    const float* qkvW   = (const float*)d_in[7];
    const float* qkvb   = (const float*)d_in[8];
    const float* outW   = (const float*)d_in[9];
    const float* outb   = (const float*)d_in[10];
    const float* w1a = (const float*)d_in[11]; const float* b1a = (const float*)d_in[12];
    const float* ga  = (const float*)d_in[13]; const float* bba = (const float*)d_in[14];
    const float* w2a = (const float*)d_in[15]; const float* b2a = (const float*)d_in[16];
    const float* w1b = (const float*)d_in[17]; const float* b1b = (const float*)d_in[18];
    const float* gb  = (const float*)d_in[19]; const float* bbb = (const float*)d_in[20];
    const float* w2b = (const float*)d_in[21]; const float* b2b = (const float*)d_in[22];
    const float* w1c = (const float*)d_in[23]; const float* b1c = (const float*)d_in[24];
    const float* gc  = (const float*)d_in[25]; const float* bbc = (const float*)d_in[26];
    const float* w2c = (const float*)d_in[27]; const float* b2c = (const float*)d_in[28];
    float* out = (float*)d_out;

    k_cent<<<NPENTA, 256>>>(penta);
    k_gemm_proj<<<dim3(P_DIM / 64, ROWS / 128), 256>>>(X, projW, projb);
    k_lgn<<<ROWS, 128>>>(lng, lnb);
    k_gemm_scores<<<dim3(NPENTA / 64, ROWS / 128), 256>>>();
    k_anchor_reduce<<<ROWS / 256, 256>>>();
    k_gemm_qkv<<<dim3(3 * P_DIM / 64, ROWS / 128), 256>>>(qkvW, qkvb);
    k_topk<<<B_ * NPENTA, 256>>>(poss);
    k_attention<<<ROWS, 256>>>();
    k_attmean1<<<512, 128>>>();
    k_attmean2<<<8, 128>>>();
    k_pool<<<8, 128>>>(outW, outb);

    k_mlpA<<<28, 128>>>(w1a, b1a, w1b, b1b, w1c, b1c);
    k_mlpB<<<6, 256>>>(ga, bba, gb, bbb, gc, bbc);
    k_mlpC<<<14, 128>>>(w2a, b2a, w2b, b2b, w2c, b2c, out);
}